// round 3
// baseline (speedup 1.0000x reference)
#include <cuda_runtime.h>
#include <math.h>
#include <stdint.h>

#define D 128
#define MAXN 50048
#define TPB 256

// ---------------- scratch (static device globals; no allocations) ----------------
__device__ __align__(16) float  g_emb[4][(size_t)MAXN * D];    // layers 0/1 embeddings; later F_l fusion buffers
__device__ __align__(16) float  g_h  [4][(size_t)MAXN * D];    // GEMM outputs / attention O / scratch
__device__ __align__(16) float  g_agg[4][(size_t)MAXN * D];    // aggregation; after layer 2 holds final embs (stk source)
__device__ __align__(16) float  g_qkv[4][(size_t)MAXN * 384];  // MHA qkv
__device__ __align__(16) float  g_deg [4][MAXN];
__device__ __align__(16) float  g_dinv[4][MAXN];
__device__ __align__(16) float  g_rels[4][D];
__device__ double g_sum[D];
__device__ double g_sumsq[D];
__device__ float  g_scale[D];
__device__ float  g_shift[D];
__device__ double g_scores[4];
__device__ float  g_coef[4];

// ---------------- init: broadcast features to 4 emb buffers, permute rels, zero scores ----
__global__ void k_init(const float* __restrict__ feat, const float* __restrict__ rel_emb, int Nn) {
    size_t idx = (size_t)blockIdx.x * blockDim.x + threadIdx.x;
    size_t tot = (size_t)Nn * D;
    if (idx < tot) {
        float v = feat[idx];
        g_emb[0][idx] = v; g_emb[1][idx] = v; g_emb[2][idx] = v; g_emb[3][idx] = v;
    }
    if (idx < 4 * D) {
        const int perm[4] = {3, 0, 1, 2};
        int r = (int)(idx / D), j = (int)(idx % D);
        g_rels[r][j] = rel_emb[perm[r] * D + j];
    }
    if (idx < 4) g_scores[idx] = 0.0;
}

__global__ void k_zero_deg() {
    size_t idx = (size_t)blockIdx.x * blockDim.x + threadIdx.x;
    if (idx < 4 * (size_t)MAXN) ((float*)g_deg)[idx] = 0.0f;
}

__global__ void k_deg(const int* __restrict__ edge, int E) {
    const int perm[4] = {3, 0, 1, 2};
    int r = blockIdx.y;
    const int* dst = edge + ((size_t)perm[r] * 2 + 1) * E;
    int t = blockIdx.x * blockDim.x + threadIdx.x;
    if (t < E) atomicAdd(&g_deg[r][dst[t]], 1.0f);
}

__global__ void k_dinv(int Nn) {
    int idx = blockIdx.x * blockDim.x + threadIdx.x;
    if (idx < 4 * Nn) {
        int r = idx / Nn, n = idx % Nn;
        g_dinv[r][n] = rsqrtf(g_deg[r][n] + 1.0f);
    }
}

// ---------------- GEMM: C[M,N] = (A * colscale?) @ B(^T?) (+ bias?) ----------------
// BM=64 BN=64 BK=16, 256 threads, 4x4 microtile.
// GCN_EPI: additionally write Cagg = C * dinv[row]^2 + bias2 (fused self-loop init).
// NOTE: Cagg must NOT alias A (cross-block RAW).
template <bool TRANSB, bool SCALE_A, bool BIAS, bool GCN_EPI>
__global__ void __launch_bounds__(256) k_gemm(
    const float* __restrict__ A, const float* __restrict__ B, float* __restrict__ C,
    int M, int N, int K,
    const float* __restrict__ colscale, const float* __restrict__ bias,
    float* __restrict__ Cagg, const float* __restrict__ dinv, const float* __restrict__ bias2)
{
    __shared__ float As[16][68];
    __shared__ float Bs[16][68];
    int tid = threadIdx.x;
    int bm = blockIdx.y * 64;
    int bn = blockIdx.x * 64;
    int tx = tid & 15, ty = tid >> 4;

    int a_row = tid >> 2;              // 0..63
    int a_col = (tid & 3) * 4;         // 0,4,8,12

    float acc[4][4];
    #pragma unroll
    for (int i = 0; i < 4; i++)
        #pragma unroll
        for (int j = 0; j < 4; j++) acc[i][j] = 0.0f;

    for (int k0 = 0; k0 < K; k0 += 16) {
        // A tile (64 x 16), stored transposed As[k][m]
        float4 av = make_float4(0.f, 0.f, 0.f, 0.f);
        if (bm + a_row < M)
            av = *reinterpret_cast<const float4*>(A + (size_t)(bm + a_row) * K + k0 + a_col);
        if (SCALE_A) {
            av.x *= colscale[k0 + a_col + 0];
            av.y *= colscale[k0 + a_col + 1];
            av.z *= colscale[k0 + a_col + 2];
            av.w *= colscale[k0 + a_col + 3];
        }
        As[a_col + 0][a_row] = av.x;
        As[a_col + 1][a_row] = av.y;
        As[a_col + 2][a_row] = av.z;
        As[a_col + 3][a_row] = av.w;

        // B tile (16 x 64)
        if (!TRANSB) {
            int b_row = tid >> 4;          // k
            int b_col = (tid & 15) * 4;    // n
            float4 bv = *reinterpret_cast<const float4*>(B + (size_t)(k0 + b_row) * N + bn + b_col);
            *reinterpret_cast<float4*>(&Bs[b_row][b_col]) = bv;
        } else {
            int nn = tid >> 2;             // 0..63
            int kk = (tid & 3) * 4;        // 0..12
            float4 bv = *reinterpret_cast<const float4*>(B + (size_t)(bn + nn) * K + k0 + kk);
            Bs[kk + 0][nn] = bv.x;
            Bs[kk + 1][nn] = bv.y;
            Bs[kk + 2][nn] = bv.z;
            Bs[kk + 3][nn] = bv.w;
        }
        __syncthreads();

        #pragma unroll
        for (int k = 0; k < 16; k++) {
            float a[4], b[4];
            #pragma unroll
            for (int i = 0; i < 4; i++) a[i] = As[k][ty * 4 + i];
            #pragma unroll
            for (int j = 0; j < 4; j++) b[j] = Bs[k][tx * 4 + j];
            #pragma unroll
            for (int i = 0; i < 4; i++)
                #pragma unroll
                for (int j = 0; j < 4; j++) acc[i][j] = fmaf(a[i], b[j], acc[i][j]);
        }
        __syncthreads();
    }

    #pragma unroll
    for (int i = 0; i < 4; i++) {
        int row = bm + ty * 4 + i;
        if (row >= M) continue;
        int col = bn + tx * 4;
        float4 out;
        out.x = acc[i][0]; out.y = acc[i][1]; out.z = acc[i][2]; out.w = acc[i][3];
        if (BIAS) {
            out.x += bias[col + 0]; out.y += bias[col + 1];
            out.z += bias[col + 2]; out.w += bias[col + 3];
        }
        *reinterpret_cast<float4*>(C + (size_t)row * N + col) = out;
        if (GCN_EPI) {
            float di = dinv[row];
            float d2 = di * di;
            float4 ag;
            ag.x = out.x * d2 + bias2[col + 0];
            ag.y = out.y * d2 + bias2[col + 1];
            ag.z = out.z * d2 + bias2[col + 2];
            ag.w = out.w * d2 + bias2[col + 3];
            *reinterpret_cast<float4*>(Cagg + (size_t)row * N + col) = ag;
        }
    }
}

// ---------------- edge scatter: agg[dst] += h[src] * dinv[src]*dinv[dst] ----------------
__global__ void k_scatter(const float* __restrict__ h, float* __restrict__ agg,
                          const int* __restrict__ src, const int* __restrict__ dst,
                          const float* __restrict__ dinv, int E) {
    int gt = blockIdx.x * blockDim.x + threadIdx.x;
    int e = gt >> 5;
    int lane = gt & 31;
    if (e >= E) return;
    int s = src[e], d = dst[e];
    float c = dinv[s] * dinv[d];
    float4 hv = reinterpret_cast<const float4*>(h + (size_t)s * D)[lane];
    float* ap = agg + (size_t)d * D + lane * 4;
    atomicAdd(ap + 0, hv.x * c);
    atomicAdd(ap + 1, hv.y * c);
    atomicAdd(ap + 2, hv.z * c);
    atomicAdd(ap + 3, hv.w * c);
}

// ---------------- BatchNorm ----------------
__global__ void k_bn_zero() {
    int j = threadIdx.x;
    if (j < D) { g_sum[j] = 0.0; g_sumsq[j] = 0.0; }
}

__global__ void k_bn_stats(const float* __restrict__ x, int Nn) {
    int j = threadIdx.x;                 // 128 threads, one per column
    int r0 = blockIdx.x * 256;
    int r1 = min(r0 + 256, Nn);
    double s = 0.0, s2 = 0.0;
    for (int r = r0; r < r1; r++) {
        float v = x[(size_t)r * D + j];
        s += v; s2 += (double)v * v;
    }
    atomicAdd(&g_sum[j], s);
    atomicAdd(&g_sumsq[j], s2);
}

__global__ void k_bn_final(const float* __restrict__ gamma, const float* __restrict__ beta, int Nn) {
    int j = threadIdx.x;
    double mean = g_sum[j] / Nn;
    double var = g_sumsq[j] / Nn - mean * mean;
    float sc = gamma[j] * (float)(1.0 / sqrt(var + 1e-5));
    g_scale[j] = sc;
    g_shift[j] = beta[j] - (float)mean * sc;
}

__global__ void k_bn_apply(const float* __restrict__ agg, float* __restrict__ emb, int Nn) {
    size_t idx = (size_t)blockIdx.x * blockDim.x + threadIdx.x;
    if (idx >= (size_t)Nn * D) return;
    int j = (int)(idx & 127);
    float v = agg[idx] * g_scale[j] + g_shift[j];
    v = v > 0.0f ? v : 0.01f * v;
    emb[idx] += v;
}

// ---------------- rels update: rels = rels @ Wrt^T + brt ----------------
__global__ void k_rels_update(const float* __restrict__ Wrt, const float* __restrict__ brt) {
    __shared__ float cur[4 * D];
    int t = threadIdx.x;  // 512 threads
    cur[t] = ((float*)g_rels)[t];
    __syncthreads();
    int r = t >> 7, j = t & 127;
    float s = brt[j];
    #pragma unroll 8
    for (int k = 0; k < D; k++) s = fmaf(cur[r * D + k], Wrt[j * D + k], s);
    ((float*)g_rels)[t] = s;
}

// ---------------- attention (L=4, 4 heads, hd=32): one warp per (node, head) ----
__global__ void k_attn(int Nn) {
    int gw = (blockIdx.x * blockDim.x + threadIdx.x) >> 5;
    int lane = threadIdx.x & 31;
    if (gw >= Nn * 4) return;
    int n = gw >> 2, h = gw & 3;

    float q[4], kk[4], v[4];
    #pragma unroll
    for (int l = 0; l < 4; l++) {
        const float* base = g_qkv[l] + (size_t)n * 384 + h * 32 + lane;
        q[l]  = base[0] * 0.17677669529663687f;  // 1/sqrt(32)
        kk[l] = base[128];
        v[l]  = base[256];
    }
    float sc[4][4];
    #pragma unroll
    for (int l = 0; l < 4; l++)
        #pragma unroll
        for (int m = 0; m < 4; m++) {
            float p = q[l] * kk[m];
            p += __shfl_xor_sync(0xFFFFFFFFu, p, 16);
            p += __shfl_xor_sync(0xFFFFFFFFu, p, 8);
            p += __shfl_xor_sync(0xFFFFFFFFu, p, 4);
            p += __shfl_xor_sync(0xFFFFFFFFu, p, 2);
            p += __shfl_xor_sync(0xFFFFFFFFu, p, 1);
            sc[l][m] = p;
        }
    #pragma unroll
    for (int l = 0; l < 4; l++) {
        float mx = fmaxf(fmaxf(sc[l][0], sc[l][1]), fmaxf(sc[l][2], sc[l][3]));
        float e0 = expf(sc[l][0] - mx), e1 = expf(sc[l][1] - mx);
        float e2 = expf(sc[l][2] - mx), e3 = expf(sc[l][3] - mx);
        float inv = 1.0f / (e0 + e1 + e2 + e3);
        float o = (e0 * v[0] + e1 * v[1] + e2 * v[2] + e3 * v[3]) * inv;
        g_h[l][(size_t)n * D + h * 32 + lane] = o;
    }
}

// ---------------- blend: F = F*alpha_l + (1-alpha_l)*stk ----------------
__global__ void k_blend(float* __restrict__ F, const float* __restrict__ stk,
                        const float* __restrict__ alphas, int l, int Nn) {
    size_t idx = (size_t)blockIdx.x * blockDim.x + threadIdx.x;
    if (idx >= (size_t)Nn * D) return;
    float a = alphas[l];
    F[idx] = F[idx] * a + (1.0f - a) * stk[idx];
}

// ---------------- score: sum_n sum_j lrelu(G[n,j])*q[j] -> g_scores[l] ----------------
__global__ void k_score(const float* __restrict__ G, const float* __restrict__ q, int l, int Nn) {
    __shared__ double sh[256];
    size_t tot = (size_t)Nn * D;
    double acc = 0.0;
    for (size_t idx = (size_t)blockIdx.x * blockDim.x + threadIdx.x; idx < tot;
         idx += (size_t)gridDim.x * blockDim.x) {
        float v = G[idx];
        v = v > 0.0f ? v : 0.01f * v;
        acc += (double)v * q[idx & 127];
    }
    sh[threadIdx.x] = acc;
    __syncthreads();
    for (int s = 128; s > 0; s >>= 1) {
        if (threadIdx.x < s) sh[threadIdx.x] += sh[threadIdx.x + s];
        __syncthreads();
    }
    if (threadIdx.x == 0) atomicAdd(&g_scores[l], sh[0]);
}

// ---------------- coef: softmax over [S0,S1,S3,S2], map back to F indices ----------------
__global__ void k_coef(int Nn) {
    double sv[4] = { g_scores[0] / Nn, g_scores[1] / Nn, g_scores[3] / Nn, g_scores[2] / Nn };
    double mx = sv[0];
    for (int i = 1; i < 4; i++) mx = sv[i] > mx ? sv[i] : mx;
    double e[4], ss = 0.0;
    for (int i = 0; i < 4; i++) { e[i] = exp(sv[i] - mx); ss += e[i]; }
    double w[4];
    for (int i = 0; i < 4; i++) w[i] = e[i] / ss;
    // region = w0*F0 + w1*F1 + w2*F3 + w3*F2
    g_coef[0] = (float)w[0];
    g_coef[1] = (float)w[1];
    g_coef[2] = (float)w[3];
    g_coef[3] = (float)w[2];
}

// ---------------- final outputs (F buffers now live in g_emb) ----------------
__global__ void k_final(float* __restrict__ out, int Nn) {
    size_t idx = (size_t)blockIdx.x * blockDim.x + threadIdx.x;
    size_t ND = (size_t)Nn * D;
    if (idx >= ND) return;
    int j = (int)(idx & 127);
    float r = g_coef[0] * g_emb[0][idx] + g_coef[1] * g_emb[1][idx]
            + g_coef[2] * g_emb[2][idx] + g_coef[3] * g_emb[3][idx];
    out[idx]          = r;
    out[ND + idx]     = r * g_rels[3][j];
    out[2 * ND + idx] = r * g_rels[0][j];
    out[3 * ND + idx] = r * g_rels[1][j];
    out[4 * ND + idx] = r * g_rels[2][j];
}

// ---------------- host orchestration ----------------
extern "C" void kernel_launch(void* const* d_in, const int* in_sizes, int n_in,
                              void* d_out, int out_size) {
    const float* features   = (const float*)d_in[0];
    const float* rel_emb    = (const float*)d_in[1];
    const int*   edge_index = (const int*)  d_in[2];
    const float* W_gcn      = (const float*)d_in[3];
    const float* b_gcn      = (const float*)d_in[4];
    const float* bn_gamma   = (const float*)d_in[5];
    const float* bn_beta    = (const float*)d_in[6];
    const float* W_rt       = (const float*)d_in[7];
    const float* b_rt       = (const float*)d_in[8];
    const float* attn_w_in  = (const float*)d_in[9];
    const float* attn_b_in  = (const float*)d_in[10];
    const float* attn_w_out = (const float*)d_in[11];
    const float* attn_b_out = (const float*)d_in[12];
    const float* alphas     = (const float*)d_in[13];
    const float* fusion_q   = (const float*)d_in[14];
    const float* fusion_w   = (const float*)d_in[15];
    const float* fusion_b   = (const float*)d_in[16];

    int Nn = in_sizes[0] / D;
    int E  = in_sizes[2] / 8;
    if (Nn > MAXN) return;

    static float *emb = nullptr, *h, *agg, *qkv, *dinv, *rels;
    if (!emb) {
        cudaGetSymbolAddress((void**)&emb,  g_emb);
        cudaGetSymbolAddress((void**)&h,    g_h);
        cudaGetSymbolAddress((void**)&agg,  g_agg);
        cudaGetSymbolAddress((void**)&qkv,  g_qkv);
        cudaGetSymbolAddress((void**)&dinv, g_dinv);
        cudaGetSymbolAddress((void**)&rels, g_rels);
    }

    static const int PERM[4] = {3, 0, 1, 2};   // relation processing order
    static const int SMAP[4] = {3, 0, 2, 1};   // stack order -> processing-order index

    size_t ND = (size_t)Nn * D;
    int gElem = (int)((ND + TPB - 1) / TPB);

    k_init<<<gElem, TPB>>>(features, rel_emb, Nn);
    k_zero_deg<<<(4 * MAXN + TPB - 1) / TPB, TPB>>>();
    {
        dim3 gdeg((E + TPB - 1) / TPB, 4);
        k_deg<<<gdeg, TPB>>>(edge_index, E);
    }
    k_dinv<<<(4 * Nn + TPB - 1) / TPB, TPB>>>(Nn);

    dim3 gemm_grid_d(D / 64, (Nn + 63) / 64);

    for (int i = 0; i < 3; i++) {
        const float* Wg = W_gcn + (size_t)i * D * D;
        const float* bg = b_gcn + (size_t)i * D;
        for (int r = 0; r < 4; r++) {
            float* er = emb + (size_t)r * MAXN * D;
            float* hr = h   + (size_t)r * MAXN * D;
            float* ar = agg + (size_t)r * MAXN * D;   // NEVER aliases er (fixes in-place RAW race)
            const float* dr = dinv + (size_t)r * MAXN;

            // h = (emb * rels_r) @ W_gcn[i] ; fused: agg = h*dinv^2 + b  (self loop + bias)
            k_gemm<false, true, false, true><<<gemm_grid_d, 256>>>(
                er, Wg, hr, Nn, D, D, rels + r * D, nullptr, ar, dr, bg);
            // agg += scatter(h[src] * dinv[src]*dinv[dst] at dst)
            const int* srcp = edge_index + ((size_t)PERM[r] * 2) * E;
            const int* dstp = srcp + E;
            k_scatter<<<(int)(((size_t)E * 32 + TPB - 1) / TPB), TPB>>>(hr, ar, srcp, dstp, dr, E);

            if (i < 2) {
                k_bn_zero<<<1, 128>>>();
                k_bn_stats<<<(Nn + 255) / 256, 128>>>(ar, Nn);
                k_bn_final<<<1, 128>>>(bn_gamma + (size_t)i * D, bn_beta + (size_t)i * D, Nn);
                k_bn_apply<<<gElem, TPB>>>(ar, er, Nn);  // emb += lrelu(bn(agg))
            }
            // i == 2: final embeddings stay in agg[r]
        }
        k_rels_update<<<1, 512>>>(W_rt + (size_t)i * D * D, b_rt + (size_t)i * D);
    }

    // ---- MHA over stacked embeddings stk[l] = agg[SMAP[l]] ----
    dim3 gemm_grid_qkv(384 / 64, (Nn + 63) / 64);
    for (int l = 0; l < 4; l++) {
        const float* A = agg + (size_t)SMAP[l] * MAXN * D;
        k_gemm<true, false, true, false><<<gemm_grid_qkv, 256>>>(A, attn_w_in,
            qkv + (size_t)l * MAXN * 384, Nn, 384, D, nullptr, attn_b_in,
            nullptr, nullptr, nullptr);
    }
    k_attn<<<(int)(((size_t)Nn * 128 + TPB - 1) / TPB), TPB>>>(Nn);
    // out-proj: fusion_l -> emb[l] (emb free after QKV)
    for (int l = 0; l < 4; l++) {
        k_gemm<true, false, true, false><<<gemm_grid_d, 256>>>(h + (size_t)l * MAXN * D, attn_w_out,
            emb + (size_t)l * MAXN * D, Nn, D, D, nullptr, attn_b_out,
            nullptr, nullptr, nullptr);
    }
    // blend: F_l = fusion_l * a_l + (1 - a_l) * stk_l   (in place in emb[l])
    for (int l = 0; l < 4; l++) {
        k_blend<<<gElem, TPB>>>(emb + (size_t)l * MAXN * D,
                                agg + (size_t)SMAP[l] * MAXN * D, alphas, l, Nn);
    }
    // scores
    for (int l = 0; l < 4; l++) {
        k_gemm<true, false, true, false><<<gemm_grid_d, 256>>>(emb + (size_t)l * MAXN * D, fusion_w,
            h, Nn, D, D, nullptr, fusion_b, nullptr, nullptr, nullptr);  // g_h[0] scratch
        k_score<<<512, 256>>>(h, fusion_q, l, Nn);
    }
    k_coef<<<1, 1>>>(Nn);
    k_final<<<gElem, TPB>>>((float*)d_out, Nn);
}

// round 4
// speedup vs baseline: 2.0707x; 2.0707x over previous
#include <cuda_runtime.h>
#include <math.h>
#include <stdint.h>

#define D 128
#define MAXN 50048
#define EMAX 409600
#define TPB 256

// ---------------- scratch (static device globals; no allocations) ----------------
__device__ __align__(16) float g_emb[4][(size_t)MAXN * D];   // layers 0/1 embeddings; later F_l fusion buffers
__device__ __align__(16) float g_h  [4][(size_t)MAXN * D];   // GEMM outputs / attention O
__device__ __align__(16) float g_agg[4][(size_t)MAXN * D];   // aggregation; after layer 2 = final embs (stk)
__device__ __align__(16) float g_qkv[4][(size_t)MAXN * 384]; // MHA qkv
__device__ int   g_cnt   [4][MAXN];
__device__ int   g_rowptr[4][MAXN + 1];
__device__ int   g_wofs  [4][MAXN];
__device__ int   g_csr_src[4][EMAX];
__device__ float g_csr_c [4][EMAX];
__device__ __align__(16) float g_dinv[4][MAXN];
__device__ __align__(16) float g_rels[4][D];
__device__ double g_sum[D];
__device__ double g_sumsq[D];
__device__ float  g_scale[D];
__device__ float  g_shift[D];
__device__ double g_scores[4];
__device__ float  g_coef[4];

// ---------------- helpers ----------------
__device__ __forceinline__ uint32_t f2tf(float x) {
    uint32_t u;
    asm("cvt.rna.tf32.f32 %0, %1;" : "=r"(u) : "f"(x));
    return u;
}

__device__ __forceinline__ void mma_tf32(float* c, const uint32_t* a, const uint32_t* b) {
    asm volatile(
        "mma.sync.aligned.m16n8k8.row.col.f32.tf32.tf32.f32 "
        "{%0,%1,%2,%3}, {%4,%5,%6,%7}, {%8,%9}, {%0,%1,%2,%3};"
        : "+f"(c[0]), "+f"(c[1]), "+f"(c[2]), "+f"(c[3])
        : "r"(a[0]), "r"(a[1]), "r"(a[2]), "r"(a[3]), "r"(b[0]), "r"(b[1]));
}

// ---------------- init: broadcast features, permute rels, zero counters/scores ----
__global__ void k_init(const float* __restrict__ feat, const float* __restrict__ rel_emb, int Nn) {
    size_t idx = (size_t)blockIdx.x * blockDim.x + threadIdx.x;
    size_t tot = (size_t)Nn * D;
    if (idx < tot) {
        float v = feat[idx];
        g_emb[0][idx] = v; g_emb[1][idx] = v; g_emb[2][idx] = v; g_emb[3][idx] = v;
    }
    if (idx < 4 * (size_t)MAXN) ((int*)g_cnt)[idx] = 0;
    if (idx < 4 * D) {
        const int perm[4] = {3, 0, 1, 2};
        int r = (int)(idx / D), j = (int)(idx % D);
        g_rels[r][j] = rel_emb[perm[r] * D + j];
    }
    if (idx < 4) g_scores[idx] = 0.0;
}

// ---------------- CSR build ----------------
__global__ void k_hist(const int* __restrict__ edge, int E) {
    const int perm[4] = {3, 0, 1, 2};
    int r = blockIdx.y;
    const int* dst = edge + ((size_t)perm[r] * 2 + 1) * E;
    int t = blockIdx.x * blockDim.x + threadIdx.x;
    if (t < E) atomicAdd(&g_cnt[r][dst[t]], 1);
}

__global__ void k_dinv(int Nn) {
    int idx = blockIdx.x * blockDim.x + threadIdx.x;
    if (idx < 4 * Nn) {
        int r = idx / Nn, n = idx % Nn;
        g_dinv[r][n] = rsqrtf((float)g_cnt[r][n] + 1.0f);
    }
}

// one block per relation, 1024 threads: exclusive scan of counts -> rowptr, wofs
__global__ void k_scan(int Nn) {
    int r = blockIdx.x;
    int t = threadIdx.x;
    __shared__ int warp_sums[32];
    __shared__ int s_carry;
    if (t == 0) s_carry = 0;
    __syncthreads();
    for (int base = 0; base < Nn; base += 1024) {
        int i = base + t;
        int v = (i < Nn) ? g_cnt[r][i] : 0;
        int x = v;
        #pragma unroll
        for (int o = 1; o < 32; o <<= 1) {
            int y = __shfl_up_sync(0xFFFFFFFFu, x, o);
            if ((t & 31) >= o) x += y;
        }
        if ((t & 31) == 31) warp_sums[t >> 5] = x;
        __syncthreads();
        if (t < 32) {
            int ws = warp_sums[t];
            #pragma unroll
            for (int o = 1; o < 32; o <<= 1) {
                int y = __shfl_up_sync(0xFFFFFFFFu, ws, o);
                if (t >= o) ws += y;
            }
            warp_sums[t] = ws;
        }
        __syncthreads();
        int warp_off = (t >= 32) ? warp_sums[(t >> 5) - 1] : 0;
        int incl = x + warp_off + s_carry;
        int excl = incl - v;
        if (i < Nn) { g_rowptr[r][i] = excl; g_wofs[r][i] = excl; }
        __syncthreads();
        if (t == 1023) s_carry = incl;
        __syncthreads();
    }
    if (t == 0) g_rowptr[r][Nn] = s_carry;
}

__global__ void k_fill(const int* __restrict__ edge, int E) {
    const int perm[4] = {3, 0, 1, 2};
    int r = blockIdx.y;
    const int* src = edge + ((size_t)perm[r] * 2) * E;
    const int* dst = src + E;
    int e = blockIdx.x * blockDim.x + threadIdx.x;
    if (e >= E) return;
    int s = src[e], d = dst[e];
    int pos = atomicAdd(&g_wofs[r][d], 1);
    g_csr_src[r][pos] = s;
    g_csr_c[r][pos] = g_dinv[r][s] * g_dinv[r][d];
}

// ---------------- TF32 tensor-core GEMM ----------------
// C[M,N] = (A * colscale?) @ B(^T?) (+bias?), BM=128 BN=64 BK=32, 256 threads.
// EPI: 0 = plain store; 1 = blend  C = (acc+bias)*alpha + (1-alpha)*stk;
//      2 = score (no store): atomically accumulate sum(lrelu(acc+bias)*q) into score_dst.
template <bool TRANSB, bool SCALE_A, bool BIAS, int EPI>
__global__ void __launch_bounds__(256) k_gemm_tf32(
    const float* __restrict__ A, const float* __restrict__ Bm, float* __restrict__ C,
    int M, int N, int K,
    const float* __restrict__ colscale, const float* __restrict__ bias,
    const float* __restrict__ ep_stk_or_q, const float* __restrict__ ep_alpha,
    double* __restrict__ score_dst)
{
    __shared__ uint32_t As[128][36];   // [m][k], stride 36 -> conflict-free frag loads
    __shared__ uint32_t Bs[64][36];    // [n][k]
    const int tid  = threadIdx.x;
    const int lane = tid & 31;
    const int wid  = tid >> 5;
    const int bm = blockIdx.y * 128;
    const int bn = blockIdx.x * 64;
    const int warp_m = (wid >> 1) * 32;
    const int warp_n = (wid & 1) * 32;

    float acc[2][4][4];
    #pragma unroll
    for (int i = 0; i < 2; i++)
        #pragma unroll
        for (int j = 0; j < 4; j++)
            #pragma unroll
            for (int q = 0; q < 4; q++) acc[i][j][q] = 0.0f;

    for (int k0 = 0; k0 < K; k0 += 32) {
        // A: lane = k, coalesced 128B rows; scalar stores conflict-free
        {
            int ka = tid & 31;
            float cs = SCALE_A ? colscale[k0 + ka] : 1.0f;
            int m0 = tid >> 5;
            #pragma unroll
            for (int i = 0; i < 16; i++) {
                int m = m0 + i * 8;
                float v = 0.0f;
                if (bm + m < M) v = A[(size_t)(bm + m) * K + k0 + ka];
                As[m][ka] = f2tf(v * cs);
            }
        }
        if (!TRANSB) {
            // global B[k][n]: lane spans n (coalesced); store Bs[n][k]
            int n = tid & 63;
            int kr0 = tid >> 6;
            #pragma unroll
            for (int i = 0; i < 8; i++) {
                int kr = kr0 + i * 4;
                Bs[n][kr] = f2tf(Bm[(size_t)(k0 + kr) * N + bn + n]);
            }
        } else {
            // global B[n][k]: lane spans k (coalesced); store Bs[n][k]
            int kb = tid & 31;
            int n0 = tid >> 5;
            #pragma unroll
            for (int i = 0; i < 8; i++) {
                int n = n0 + i * 8;
                Bs[n][kb] = f2tf(Bm[(size_t)(bn + n) * K + k0 + kb]);
            }
        }
        __syncthreads();

        int r0 = lane >> 2, c0 = lane & 3;
        #pragma unroll
        for (int ks = 0; ks < 32; ks += 8) {
            uint32_t a[2][4], b[4][2];
            #pragma unroll
            for (int fm = 0; fm < 2; fm++) {
                int mb = warp_m + fm * 16;
                a[fm][0] = As[mb + r0][ks + c0];
                a[fm][1] = As[mb + 8 + r0][ks + c0];
                a[fm][2] = As[mb + r0][ks + 4 + c0];
                a[fm][3] = As[mb + 8 + r0][ks + 4 + c0];
            }
            #pragma unroll
            for (int fn = 0; fn < 4; fn++) {
                int nb = warp_n + fn * 8 + r0;
                b[fn][0] = Bs[nb][ks + c0];
                b[fn][1] = Bs[nb][ks + 4 + c0];
            }
            #pragma unroll
            for (int fm = 0; fm < 2; fm++)
                #pragma unroll
                for (int fn = 0; fn < 4; fn++)
                    mma_tf32(acc[fm][fn], a[fm], b[fn]);
        }
        __syncthreads();
    }

    // epilogue
    int r0 = lane >> 2, cc = (lane & 3) * 2;
    float alpha = 0.f, one_m_alpha = 0.f;
    if (EPI == 1) { alpha = ep_alpha[0]; one_m_alpha = 1.0f - alpha; }
    float score_local = 0.0f;

    #pragma unroll
    for (int fm = 0; fm < 2; fm++) {
        #pragma unroll
        for (int fn = 0; fn < 4; fn++) {
            int row = bm + warp_m + fm * 16 + r0;
            int col = bn + warp_n + fn * 8 + cc;
            float b0 = BIAS ? bias[col] : 0.0f;
            float b1 = BIAS ? bias[col + 1] : 0.0f;
            float v00 = acc[fm][fn][0] + b0, v01 = acc[fm][fn][1] + b1;
            float v10 = acc[fm][fn][2] + b0, v11 = acc[fm][fn][3] + b1;
            if (EPI == 0) {
                if (row < M)     *(float2*)(C + (size_t)row * N + col)       = make_float2(v00, v01);
                if (row + 8 < M) *(float2*)(C + (size_t)(row + 8) * N + col) = make_float2(v10, v11);
            } else if (EPI == 1) {
                if (row < M) {
                    const float2 s = *(const float2*)(ep_stk_or_q + (size_t)row * N + col);
                    *(float2*)(C + (size_t)row * N + col) =
                        make_float2(v00 * alpha + one_m_alpha * s.x, v01 * alpha + one_m_alpha * s.y);
                }
                if (row + 8 < M) {
                    const float2 s = *(const float2*)(ep_stk_or_q + (size_t)(row + 8) * N + col);
                    *(float2*)(C + (size_t)(row + 8) * N + col) =
                        make_float2(v10 * alpha + one_m_alpha * s.x, v11 * alpha + one_m_alpha * s.y);
                }
            } else {  // EPI == 2: score
                float q0 = ep_stk_or_q[col], q1 = ep_stk_or_q[col + 1];
                if (row < M) {
                    float l0 = v00 > 0.f ? v00 : 0.01f * v00;
                    float l1 = v01 > 0.f ? v01 : 0.01f * v01;
                    score_local += l0 * q0 + l1 * q1;
                }
                if (row + 8 < M) {
                    float l0 = v10 > 0.f ? v10 : 0.01f * v10;
                    float l1 = v11 > 0.f ? v11 : 0.01f * v11;
                    score_local += l0 * q0 + l1 * q1;
                }
            }
        }
    }

    if (EPI == 2) {
        __shared__ float sred[8];
        #pragma unroll
        for (int o = 16; o > 0; o >>= 1)
            score_local += __shfl_xor_sync(0xFFFFFFFFu, score_local, o);
        if (lane == 0) sred[wid] = score_local;
        __syncthreads();
        if (tid == 0) {
            float tot = 0.f;
            #pragma unroll
            for (int w = 0; w < 8; w++) tot += sred[w];
            atomicAdd(score_dst, (double)tot);
        }
    }
}

// ---------------- CSR aggregation: warp per dst ----------------
// agg[d] = h[d]*dinv[d]^2 + bias + sum_{e in in(d)} h[src_e] * c_e
__global__ void k_agg(const float* __restrict__ h, float* __restrict__ agg,
                      const int* __restrict__ csr_src, const float* __restrict__ csr_c,
                      const int* __restrict__ rowptr, const float* __restrict__ dinv,
                      const float* __restrict__ bias, int Nn) {
    int gw = (blockIdx.x * blockDim.x + threadIdx.x) >> 5;
    int lane = threadIdx.x & 31;
    if (gw >= Nn) return;
    int d = gw;
    float di = dinv[d];
    float d2 = di * di;
    float4 acc = ((const float4*)(h + (size_t)d * D))[lane];
    float4 bv  = ((const float4*)bias)[lane];
    acc.x = acc.x * d2 + bv.x;
    acc.y = acc.y * d2 + bv.y;
    acc.z = acc.z * d2 + bv.z;
    acc.w = acc.w * d2 + bv.w;
    int beg = rowptr[d], end = rowptr[d + 1];
    for (int e = beg; e < end; e++) {
        int s = csr_src[e];
        float c = csr_c[e];
        float4 hv = ((const float4*)(h + (size_t)s * D))[lane];
        acc.x += hv.x * c;
        acc.y += hv.y * c;
        acc.z += hv.z * c;
        acc.w += hv.w * c;
    }
    ((float4*)(agg + (size_t)d * D))[lane] = acc;
}

// ---------------- BatchNorm ----------------
__global__ void k_bn_zero() {
    int j = threadIdx.x;
    if (j < D) { g_sum[j] = 0.0; g_sumsq[j] = 0.0; }
}

__global__ void k_bn_stats(const float* __restrict__ x, int Nn) {
    int j = threadIdx.x;
    int r0 = blockIdx.x * 256;
    int r1 = min(r0 + 256, Nn);
    double s = 0.0, s2 = 0.0;
    for (int r = r0; r < r1; r++) {
        float v = x[(size_t)r * D + j];
        s += v; s2 += (double)v * v;
    }
    atomicAdd(&g_sum[j], s);
    atomicAdd(&g_sumsq[j], s2);
}

__global__ void k_bn_final(const float* __restrict__ gamma, const float* __restrict__ beta, int Nn) {
    int j = threadIdx.x;
    double mean = g_sum[j] / Nn;
    double var = g_sumsq[j] / Nn - mean * mean;
    float sc = gamma[j] * (float)(1.0 / sqrt(var + 1e-5));
    g_scale[j] = sc;
    g_shift[j] = beta[j] - (float)mean * sc;
}

__global__ void k_bn_apply(const float* __restrict__ agg, float* __restrict__ emb, int Nn) {
    size_t idx = (size_t)blockIdx.x * blockDim.x + threadIdx.x;
    if (idx >= (size_t)Nn * D) return;
    int j = (int)(idx & 127);
    float v = agg[idx] * g_scale[j] + g_shift[j];
    v = v > 0.0f ? v : 0.01f * v;
    emb[idx] += v;
}

// ---------------- rels update: rels = rels @ Wrt^T + brt ----------------
__global__ void k_rels_update(const float* __restrict__ Wrt, const float* __restrict__ brt) {
    __shared__ float cur[4 * D];
    int t = threadIdx.x;  // 512
    cur[t] = ((float*)g_rels)[t];
    __syncthreads();
    int r = t >> 7, j = t & 127;
    float s = brt[j];
    #pragma unroll 8
    for (int k = 0; k < D; k++) s = fmaf(cur[r * D + k], Wrt[j * D + k], s);
    ((float*)g_rels)[t] = s;
}

// ---------------- attention (L=4, 4 heads, hd=32): one warp per (node, head) ----
__global__ void k_attn(int Nn) {
    int gw = (blockIdx.x * blockDim.x + threadIdx.x) >> 5;
    int lane = threadIdx.x & 31;
    if (gw >= Nn * 4) return;
    int n = gw >> 2, h = gw & 3;

    float q[4], kk[4], v[4];
    #pragma unroll
    for (int l = 0; l < 4; l++) {
        const float* base = g_qkv[l] + (size_t)n * 384 + h * 32 + lane;
        q[l]  = base[0] * 0.17677669529663687f;  // 1/sqrt(32)
        kk[l] = base[128];
        v[l]  = base[256];
    }
    float sc[4][4];
    #pragma unroll
    for (int l = 0; l < 4; l++)
        #pragma unroll
        for (int m = 0; m < 4; m++) {
            float p = q[l] * kk[m];
            p += __shfl_xor_sync(0xFFFFFFFFu, p, 16);
            p += __shfl_xor_sync(0xFFFFFFFFu, p, 8);
            p += __shfl_xor_sync(0xFFFFFFFFu, p, 4);
            p += __shfl_xor_sync(0xFFFFFFFFu, p, 2);
            p += __shfl_xor_sync(0xFFFFFFFFu, p, 1);
            sc[l][m] = p;
        }
    #pragma unroll
    for (int l = 0; l < 4; l++) {
        float mx = fmaxf(fmaxf(sc[l][0], sc[l][1]), fmaxf(sc[l][2], sc[l][3]));
        float e0 = expf(sc[l][0] - mx), e1 = expf(sc[l][1] - mx);
        float e2 = expf(sc[l][2] - mx), e3 = expf(sc[l][3] - mx);
        float inv = 1.0f / (e0 + e1 + e2 + e3);
        float o = (e0 * v[0] + e1 * v[1] + e2 * v[2] + e3 * v[3]) * inv;
        g_h[l][(size_t)n * D + h * 32 + lane] = o;
    }
}

// ---------------- coef: softmax over [S0,S1,S3,S2], mapped back ----------------
__global__ void k_coef(int Nn) {
    double sv[4] = { g_scores[0] / Nn, g_scores[1] / Nn, g_scores[3] / Nn, g_scores[2] / Nn };
    double mx = sv[0];
    for (int i = 1; i < 4; i++) mx = sv[i] > mx ? sv[i] : mx;
    double e[4], ss = 0.0;
    for (int i = 0; i < 4; i++) { e[i] = exp(sv[i] - mx); ss += e[i]; }
    double w[4];
    for (int i = 0; i < 4; i++) w[i] = e[i] / ss;
    // region = w0*F0 + w1*F1 + w2*F3 + w3*F2
    g_coef[0] = (float)w[0];
    g_coef[1] = (float)w[1];
    g_coef[2] = (float)w[3];
    g_coef[3] = (float)w[2];
}

// ---------------- final outputs (F buffers in g_emb) ----------------
__global__ void k_final(float* __restrict__ out, int Nn) {
    size_t idx = (size_t)blockIdx.x * blockDim.x + threadIdx.x;
    size_t ND = (size_t)Nn * D;
    if (idx >= ND) return;
    int j = (int)(idx & 127);
    float r = g_coef[0] * g_emb[0][idx] + g_coef[1] * g_emb[1][idx]
            + g_coef[2] * g_emb[2][idx] + g_coef[3] * g_emb[3][idx];
    out[idx]          = r;
    out[ND + idx]     = r * g_rels[3][j];
    out[2 * ND + idx] = r * g_rels[0][j];
    out[3 * ND + idx] = r * g_rels[1][j];
    out[4 * ND + idx] = r * g_rels[2][j];
}

// ---------------- host orchestration ----------------
extern "C" void kernel_launch(void* const* d_in, const int* in_sizes, int n_in,
                              void* d_out, int out_size) {
    const float* features   = (const float*)d_in[0];
    const float* rel_emb    = (const float*)d_in[1];
    const int*   edge_index = (const int*)  d_in[2];
    const float* W_gcn      = (const float*)d_in[3];
    const float* b_gcn      = (const float*)d_in[4];
    const float* bn_gamma   = (const float*)d_in[5];
    const float* bn_beta    = (const float*)d_in[6];
    const float* W_rt       = (const float*)d_in[7];
    const float* b_rt       = (const float*)d_in[8];
    const float* attn_w_in  = (const float*)d_in[9];
    const float* attn_b_in  = (const float*)d_in[10];
    const float* attn_w_out = (const float*)d_in[11];
    const float* attn_b_out = (const float*)d_in[12];
    const float* alphas     = (const float*)d_in[13];
    const float* fusion_q   = (const float*)d_in[14];
    const float* fusion_w   = (const float*)d_in[15];
    const float* fusion_b   = (const float*)d_in[16];

    int Nn = in_sizes[0] / D;
    int E  = in_sizes[2] / 8;
    if (Nn > MAXN || E > EMAX) return;

    static float *emb = nullptr, *h, *agg, *qkv, *dinv, *rels;
    static int *csr_src, *rowptr;
    static float *csr_c;
    static double *scores;
    if (!emb) {
        cudaGetSymbolAddress((void**)&emb,     g_emb);
        cudaGetSymbolAddress((void**)&h,       g_h);
        cudaGetSymbolAddress((void**)&agg,     g_agg);
        cudaGetSymbolAddress((void**)&qkv,     g_qkv);
        cudaGetSymbolAddress((void**)&dinv,    g_dinv);
        cudaGetSymbolAddress((void**)&rels,    g_rels);
        cudaGetSymbolAddress((void**)&csr_src, g_csr_src);
        cudaGetSymbolAddress((void**)&csr_c,   g_csr_c);
        cudaGetSymbolAddress((void**)&rowptr,  g_rowptr);
        cudaGetSymbolAddress((void**)&scores,  g_scores);
    }

    static const int SMAP[4] = {3, 0, 2, 1};   // stack order -> processing-order index

    size_t ND = (size_t)Nn * D;
    int gElem = (int)((ND + TPB - 1) / TPB);
    int gEdge = (E + TPB - 1) / TPB;

    k_init<<<gElem, TPB>>>(features, rel_emb, Nn);
    k_hist<<<dim3(gEdge, 4), TPB>>>(edge_index, E);
    k_dinv<<<(4 * Nn + TPB - 1) / TPB, TPB>>>(Nn);
    k_scan<<<4, 1024>>>(Nn);
    k_fill<<<dim3(gEdge, 4), TPB>>>(edge_index, E);

    dim3 grid_d(2, (Nn + 127) / 128);       // N=128
    dim3 grid_qkv(6, (Nn + 127) / 128);     // N=384
    int gAgg = (int)(((size_t)Nn * 32 + TPB - 1) / TPB);

    for (int i = 0; i < 3; i++) {
        const float* Wg = W_gcn + (size_t)i * D * D;
        const float* bg = b_gcn + (size_t)i * D;
        for (int r = 0; r < 4; r++) {
            float* er = emb + (size_t)r * MAXN * D;
            float* hr = h   + (size_t)r * MAXN * D;
            float* ar = agg + (size_t)r * MAXN * D;
            const float* dr = dinv + (size_t)r * MAXN;

            // h = (emb * rels_r) @ W_gcn[i]
            k_gemm_tf32<false, true, false, 0><<<grid_d, 256>>>(
                er, Wg, hr, Nn, D, D, rels + r * D, nullptr, nullptr, nullptr, nullptr);
            // agg = self-loop + bias + CSR gather
            k_agg<<<gAgg, TPB>>>(hr, ar, csr_src + (size_t)r * EMAX, csr_c + (size_t)r * EMAX,
                                 rowptr + (size_t)r * (MAXN + 1), dr, bg, Nn);
            if (i < 2) {
                k_bn_zero<<<1, 128>>>();
                k_bn_stats<<<(Nn + 255) / 256, 128>>>(ar, Nn);
                k_bn_final<<<1, 128>>>(bn_gamma + (size_t)i * D, bn_beta + (size_t)i * D, Nn);
                k_bn_apply<<<gElem, TPB>>>(ar, er, Nn);  // emb += lrelu(bn(agg))
            }
            // i == 2: final embeddings stay in agg[r]
        }
        k_rels_update<<<1, 512>>>(W_rt + (size_t)i * D * D, b_rt + (size_t)i * D);
    }

    // ---- MHA: QKV over stk[l] = agg[SMAP[l]] ----
    for (int l = 0; l < 4; l++) {
        const float* A = agg + (size_t)SMAP[l] * MAXN * D;
        k_gemm_tf32<true, false, true, 0><<<grid_qkv, 256>>>(
            A, attn_w_in, qkv + (size_t)l * MAXN * 384, Nn, 384, D,
            nullptr, attn_b_in, nullptr, nullptr, nullptr);
    }
    k_attn<<<(int)(((size_t)Nn * 128 + TPB - 1) / TPB), TPB>>>(Nn);
    // out-proj + fused blend: emb[l] = (attnO @ Wout^T + bout)*a_l + (1-a_l)*stk_l
    for (int l = 0; l < 4; l++) {
        k_gemm_tf32<true, false, true, 1><<<grid_d, 256>>>(
            h + (size_t)l * MAXN * D, attn_w_out, emb + (size_t)l * MAXN * D, Nn, D, D,
            nullptr, attn_b_out, agg + (size_t)SMAP[l] * MAXN * D, alphas + l, nullptr);
    }
    // scores: fused GEMM + lrelu·q reduction (no materialization)
    for (int l = 0; l < 4; l++) {
        k_gemm_tf32<true, false, true, 2><<<grid_d, 256>>>(
            emb + (size_t)l * MAXN * D, fusion_w, nullptr, Nn, D, D,
            nullptr, fusion_b, fusion_q, nullptr, scores + l);
    }
    k_coef<<<1, 1>>>(Nn);
    k_final<<<gElem, TPB>>>((float*)d_out, Nn);
}

// round 6
// speedup vs baseline: 2.8133x; 1.3586x over previous
#include <cuda_runtime.h>
#include <math.h>
#include <stdint.h>

#define D 128
#define MAXN 50048           // 391 * 128, multiple of 128
#define EMAX 409600
#define TPB 256

// ---------------- scratch (static device globals; no allocations) ----------------
__device__ __align__(16) float g_emb[4][(size_t)MAXN * D];
__device__ __align__(16) float g_h  [4][(size_t)MAXN * D];
__device__ __align__(16) float g_agg[4][(size_t)MAXN * D];
__device__ __align__(16) float g_qkv[4][(size_t)MAXN * 384];
__device__ int   g_cnt   [4][MAXN];
__device__ int   g_rowptr[4][MAXN + 1];
__device__ int   g_wofs  [4][MAXN];
__device__ int   g_psum  [4][64];
__device__ int   g_total [4];
__device__ int   g_csr_src[4][EMAX];
__device__ float g_csr_c [4][EMAX];
__device__ __align__(16) float g_dinv[4][MAXN];
__device__ __align__(16) float g_rels[4][D];
__device__ double g_sum[4][D];
__device__ double g_sumsq[4][D];
__device__ float  g_scale[4][D];
__device__ float  g_shift[4][D];
__device__ double g_scores[4];
__device__ float  g_coef[4];

// ---------------- helpers ----------------
__device__ __forceinline__ uint32_t f2tf(float x) {
    uint32_t u;
    asm("cvt.rna.tf32.f32 %0, %1;" : "=r"(u) : "f"(x));
    return u;
}
__device__ __forceinline__ void mma_tf32(float* c, const uint32_t* a, const uint32_t* b) {
    asm volatile(
        "mma.sync.aligned.m16n8k8.row.col.f32.tf32.tf32.f32 "
        "{%0,%1,%2,%3}, {%4,%5,%6,%7}, {%8,%9}, {%0,%1,%2,%3};"
        : "+f"(c[0]), "+f"(c[1]), "+f"(c[2]), "+f"(c[3])
        : "r"(a[0]), "r"(a[1]), "r"(a[2]), "r"(a[3]), "r"(b[0]), "r"(b[1]));
}
__device__ __forceinline__ void cp16(uint32_t dst, const void* src) {
    asm volatile("cp.async.cg.shared.global [%0], [%1], 16;" :: "r"(dst), "l"(src));
}

// ---------------- init ----------------
__global__ void k_init(const float* __restrict__ feat, const float* __restrict__ rel_emb, int Nn) {
    size_t idx = (size_t)blockIdx.x * blockDim.x + threadIdx.x;
    size_t tot = (size_t)Nn * D;
    if (idx < tot) {
        float v = feat[idx];
        g_emb[0][idx] = v; g_emb[1][idx] = v; g_emb[2][idx] = v; g_emb[3][idx] = v;
    }
    if (idx < 4 * (size_t)MAXN) ((int*)g_cnt)[idx] = 0;
    if (idx < 4 * D) {
        const int perm[4] = {3, 0, 1, 2};
        int r = (int)(idx / D), j = (int)(idx % D);
        g_rels[r][j] = rel_emb[perm[r] * D + j];
    }
    if (idx < 4) g_scores[idx] = 0.0;
}

// zero scratch tail rows [Nn, MAXN) so GEMM A-loads need no bounds checks
__global__ void k_zero_tail(int Nn) {
    size_t tail = (size_t)(MAXN - Nn) * D;
    size_t idx = (size_t)blockIdx.x * blockDim.x + threadIdx.x;
    if (idx >= tail) return;
    size_t o = (size_t)Nn * D + idx;
    #pragma unroll
    for (int r = 0; r < 4; r++) { g_emb[r][o] = 0.f; g_h[r][o] = 0.f; g_agg[r][o] = 0.f; }
}

// ---------------- CSR build ----------------
__global__ void k_hist(const int* __restrict__ edge, int E) {
    const int perm[4] = {3, 0, 1, 2};
    int r = blockIdx.y;
    const int* dst = edge + ((size_t)perm[r] * 2 + 1) * E;
    int t = blockIdx.x * blockDim.x + threadIdx.x;
    if (t < E) atomicAdd(&g_cnt[r][dst[t]], 1);
}

__global__ void k_dinv(int Nn) {
    int idx = blockIdx.x * blockDim.x + threadIdx.x;
    if (idx < 4 * Nn) {
        int r = idx / Nn, n = idx % Nn;
        g_dinv[r][n] = rsqrtf((float)g_cnt[r][n] + 1.0f);
    }
}

__global__ void k_scan1(int Nn) {     // grid (nb, 4) x 1024
    int r = blockIdx.y, t = threadIdx.x;
    int i = blockIdx.x * 1024 + t;
    int v = (i < Nn) ? g_cnt[r][i] : 0;
    int x = v;
    #pragma unroll
    for (int o = 1; o < 32; o <<= 1) {
        int y = __shfl_up_sync(0xFFFFFFFFu, x, o);
        if ((t & 31) >= o) x += y;
    }
    __shared__ int ws[32];
    if ((t & 31) == 31) ws[t >> 5] = x;
    __syncthreads();
    if (t < 32) {
        int y = ws[t];
        #pragma unroll
        for (int o = 1; o < 32; o <<= 1) {
            int z = __shfl_up_sync(0xFFFFFFFFu, y, o);
            if (t >= o) y += z;
        }
        ws[t] = y;
    }
    __syncthreads();
    int off = (t >= 32) ? ws[(t >> 5) - 1] : 0;
    int incl = x + off;
    if (i < Nn) g_rowptr[r][i] = incl - v;
    if (t == 1023) g_psum[r][blockIdx.x] = incl;
}

__global__ void k_scan2(int nb) {     // grid 4 x 64
    int r = blockIdx.x, t = threadIdx.x;
    int v = (t < nb) ? g_psum[r][t] : 0;
    int x = v;
    #pragma unroll
    for (int o = 1; o < 32; o <<= 1) {
        int y = __shfl_up_sync(0xFFFFFFFFu, x, o);
        if ((t & 31) >= o) x += y;
    }
    __shared__ int w2[2];
    if ((t & 31) == 31) w2[t >> 5] = x;
    __syncthreads();
    int off = (t >= 32) ? w2[0] : 0;
    int incl = x + off;
    g_psum[r][t] = incl - v;
    if (t == 63) g_total[r] = incl;
}

__global__ void k_scan3(int Nn) {     // grid (nb, 4) x 1024
    int r = blockIdx.y;
    int i = blockIdx.x * 1024 + threadIdx.x;
    if (i < Nn) {
        int val = g_rowptr[r][i] + g_psum[r][blockIdx.x];
        g_rowptr[r][i] = val;
        g_wofs[r][i] = val;
    }
    if (i == 0) g_rowptr[r][Nn] = g_total[r];
}

__global__ void k_fill(const int* __restrict__ edge, int E) {
    const int perm[4] = {3, 0, 1, 2};
    int r = blockIdx.y;
    const int* src = edge + ((size_t)perm[r] * 2) * E;
    const int* dst = src + E;
    int e = blockIdx.x * blockDim.x + threadIdx.x;
    if (e >= E) return;
    int s = src[e], d = dst[e];
    int pos = atomicAdd(&g_wofs[r][d], 1);
    g_csr_src[r][pos] = s;
    g_csr_c[r][pos] = g_dinv[r][s] * g_dinv[r][d];
}

// ---------------- batched pipelined TF32 GEMM ----------------
// BM=128 BN=128 BK=32, 256 threads, cp.async 2-stage double buffer.
// z = blockIdx.z selects batch slice via long4 offsets.
// EPI: 0 plain store (+bias), 1 blend (C = (acc+bias)*alpha[z] + (1-alpha)*stk),
//      2 score (no store; sum lrelu(acc+bias)*q -> scores[z]).
// A must have >= gridDim.y*128 valid (zeroed-tail) rows.
template <bool TRANSB, bool SCALE_A, bool BIAS, int EPI>
__global__ void __launch_bounds__(256) k_gemm_tf32(
    const float* __restrict__ A_base, long4 a_off,
    const float* __restrict__ Bm,
    float* __restrict__ C_base, long4 c_off,
    int M, int N, int K,
    const float* __restrict__ cs_base,
    const float* __restrict__ bias,
    const float* __restrict__ ep_base, long4 ep_off,
    const float* __restrict__ alphas,
    double* __restrict__ scores)
{
    extern __shared__ uint32_t sm[];
    __shared__ float s_cs[128];
    const int tid = threadIdx.x;
    const int lane = tid & 31, wid = tid >> 5;
    const int z = blockIdx.z;
    const long ao = (z == 0) ? a_off.x : (z == 1) ? a_off.y : (z == 2) ? a_off.z : a_off.w;
    const long co = (z == 0) ? c_off.x : (z == 1) ? c_off.y : (z == 2) ? c_off.z : c_off.w;
    const long eo = (z == 0) ? ep_off.x : (z == 1) ? ep_off.y : (z == 2) ? ep_off.z : ep_off.w;
    const float* A = A_base + ao;
    float* C = C_base + co;
    const int bm = blockIdx.y * 128;
    const int bn = blockIdx.x * 128;
    const int warp_m = (wid & 3) * 32;
    const int warp_n = (wid >> 2) * 64;
    const uint32_t smem_u = (uint32_t)__cvta_generic_to_shared(sm);

    if (SCALE_A && tid < 128) s_cs[tid] = cs_base[z * 128 + tid];

    float acc[2][8][4];
    #pragma unroll
    for (int i = 0; i < 2; i++)
        #pragma unroll
        for (int j = 0; j < 8; j++)
            #pragma unroll
            for (int q = 0; q < 4; q++) acc[i][j][q] = 0.0f;

    auto load_stage = [&](int st, int k0) {
        #pragma unroll
        for (int i = 0; i < 4; i++) {
            int id = tid + i * 256;
            int m = id >> 3, c = id & 7;
            cp16(smem_u + (uint32_t)(st * 4608 + m * 36 + c * 4) * 4,
                 A + (size_t)(bm + m) * K + k0 + c * 4);
        }
        if (TRANSB) {
            #pragma unroll
            for (int i = 0; i < 4; i++) {
                int id = tid + i * 256;
                int n = id >> 3, c = id & 7;
                cp16(smem_u + (uint32_t)(9216 + st * 4608 + n * 36 + c * 4) * 4,
                     Bm + (size_t)(bn + n) * K + k0 + c * 4);
            }
        } else {
            #pragma unroll
            for (int i = 0; i < 4; i++) {
                int id = tid + i * 256;
                int k = id >> 5, c = id & 31;
                cp16(smem_u + (uint32_t)(9216 + st * 4352 + k * 136 + c * 4) * 4,
                     Bm + (size_t)(k0 + k) * N + bn + c * 4);
            }
        }
    };

    const int r0 = lane >> 2, c0 = lane & 3;
    const int nk = K >> 5;

    load_stage(0, 0);
    asm volatile("cp.async.commit_group;");

    for (int kt = 0; kt < nk; kt++) {
        const int cur = kt & 1;
        const int k0g = kt << 5;
        if (kt + 1 < nk) {
            load_stage((kt + 1) & 1, (kt + 1) << 5);
            asm volatile("cp.async.commit_group;");
            asm volatile("cp.async.wait_group 1;");
        } else {
            asm volatile("cp.async.wait_group 0;");
        }
        __syncthreads();

        #pragma unroll
        for (int ks = 0; ks < 32; ks += 8) {
            uint32_t a[2][4], b[8][2];
            float cs0 = 1.0f, cs1 = 1.0f;
            if (SCALE_A) { cs0 = s_cs[k0g + ks + c0]; cs1 = s_cs[k0g + ks + 4 + c0]; }
            #pragma unroll
            for (int fm = 0; fm < 2; fm++) {
                int mb = warp_m + fm * 16;
                const uint32_t* Ab = sm + cur * 4608;
                float v0 = __uint_as_float(Ab[(mb + r0) * 36 + ks + c0]);
                float v1 = __uint_as_float(Ab[(mb + 8 + r0) * 36 + ks + c0]);
                float v2 = __uint_as_float(Ab[(mb + r0) * 36 + ks + 4 + c0]);
                float v3 = __uint_as_float(Ab[(mb + 8 + r0) * 36 + ks + 4 + c0]);
                if (SCALE_A) { v0 *= cs0; v1 *= cs0; v2 *= cs1; v3 *= cs1; }
                a[fm][0] = f2tf(v0); a[fm][1] = f2tf(v1);
                a[fm][2] = f2tf(v2); a[fm][3] = f2tf(v3);
            }
            if (TRANSB) {
                const uint32_t* Bb = sm + 9216 + cur * 4608;
                #pragma unroll
                for (int fn = 0; fn < 8; fn++) {
                    int nb = warp_n + fn * 8 + r0;
                    b[fn][0] = f2tf(__uint_as_float(Bb[nb * 36 + ks + c0]));
                    b[fn][1] = f2tf(__uint_as_float(Bb[nb * 36 + ks + 4 + c0]));
                }
            } else {
                const uint32_t* Bb = sm + 9216 + cur * 4352;
                #pragma unroll
                for (int fn = 0; fn < 8; fn++) {
                    int nb = warp_n + fn * 8 + r0;
                    b[fn][0] = f2tf(__uint_as_float(Bb[(ks + c0) * 136 + nb]));
                    b[fn][1] = f2tf(__uint_as_float(Bb[(ks + 4 + c0) * 136 + nb]));
                }
            }
            #pragma unroll
            for (int fm = 0; fm < 2; fm++)
                #pragma unroll
                for (int fn = 0; fn < 8; fn++)
                    mma_tf32(acc[fm][fn], a[fm], b[fn]);
        }
        __syncthreads();
    }

    // ---- epilogue ----
    const int cc = (lane & 3) * 2;
    float alpha = 0.f, oma = 0.f;
    if (EPI == 1) { alpha = alphas[z]; oma = 1.0f - alpha; }
    const float* EP = (EPI != 0) ? (ep_base + (EPI == 1 ? eo : 0)) : nullptr;
    float score_local = 0.0f;

    #pragma unroll
    for (int fm = 0; fm < 2; fm++) {
        #pragma unroll
        for (int fn = 0; fn < 8; fn++) {
            int row = bm + warp_m + fm * 16 + r0;
            int col = bn + warp_n + fn * 8 + cc;
            float b0 = BIAS ? bias[col] : 0.0f;
            float b1 = BIAS ? bias[col + 1] : 0.0f;
            float v00 = acc[fm][fn][0] + b0, v01 = acc[fm][fn][1] + b1;
            float v10 = acc[fm][fn][2] + b0, v11 = acc[fm][fn][3] + b1;
            if (EPI == 0) {
                if (row < M)     *(float2*)(C + (size_t)row * N + col)       = make_float2(v00, v01);
                if (row + 8 < M) *(float2*)(C + (size_t)(row + 8) * N + col) = make_float2(v10, v11);
            } else if (EPI == 1) {
                if (row < M) {
                    float2 s = *(const float2*)(EP + (size_t)row * N + col);
                    *(float2*)(C + (size_t)row * N + col) =
                        make_float2(v00 * alpha + oma * s.x, v01 * alpha + oma * s.y);
                }
                if (row + 8 < M) {
                    float2 s = *(const float2*)(EP + (size_t)(row + 8) * N + col);
                    *(float2*)(C + (size_t)(row + 8) * N + col) =
                        make_float2(v10 * alpha + oma * s.x, v11 * alpha + oma * s.y);
                }
            } else {
                float q0 = EP[col], q1 = EP[col + 1];
                if (row < M) {
                    float l0 = v00 > 0.f ? v00 : 0.01f * v00;
                    float l1 = v01 > 0.f ? v01 : 0.01f * v01;
                    score_local += l0 * q0 + l1 * q1;
                }
                if (row + 8 < M) {
                    float l0 = v10 > 0.f ? v10 : 0.01f * v10;
                    float l1 = v11 > 0.f ? v11 : 0.01f * v11;
                    score_local += l0 * q0 + l1 * q1;
                }
            }
        }
    }

    if (EPI == 2) {
        __shared__ float sred[8];
        #pragma unroll
        for (int o = 16; o > 0; o >>= 1)
            score_local += __shfl_xor_sync(0xFFFFFFFFu, score_local, o);
        if (lane == 0) sred[wid] = score_local;
        __syncthreads();
        if (tid == 0) {
            float tot = 0.f;
            #pragma unroll
            for (int w = 0; w < 8; w++) tot += sred[w];
            atomicAdd(&scores[z], (double)tot);
        }
    }
}

// ---------------- CSR aggregation (batched, warp per dst) ----------------
__global__ void k_agg(const float* __restrict__ bias, int Nn) {
    int r = blockIdx.y;
    int gw = (blockIdx.x * blockDim.x + threadIdx.x) >> 5;
    int lane = threadIdx.x & 31;
    if (gw >= Nn) return;
    const float* h = g_h[r];
    float di = g_dinv[r][gw];
    float d2 = di * di;
    float4 acc = ((const float4*)(h + (size_t)gw * D))[lane];
    float4 bv  = ((const float4*)bias)[lane];
    acc.x = acc.x * d2 + bv.x;
    acc.y = acc.y * d2 + bv.y;
    acc.z = acc.z * d2 + bv.z;
    acc.w = acc.w * d2 + bv.w;
    int beg = g_rowptr[r][gw], end = g_rowptr[r][gw + 1];
    for (int e = beg; e < end; e++) {
        int s = g_csr_src[r][e];
        float c = g_csr_c[r][e];
        float4 hv = ((const float4*)(h + (size_t)s * D))[lane];
        acc.x += hv.x * c;
        acc.y += hv.y * c;
        acc.z += hv.z * c;
        acc.w += hv.w * c;
    }
    ((float4*)(g_agg[r] + (size_t)gw * D))[lane] = acc;
}

// ---------------- BatchNorm (batched over relations) ----------------
__global__ void k_bn_zero() {
    int t = threadIdx.x;   // 512
    ((double*)g_sum)[t] = 0.0;
    ((double*)g_sumsq)[t] = 0.0;
}

__global__ void k_bn_stats(int Nn) {   // grid (nb, 4) x 128
    int r = blockIdx.y;
    int j = threadIdx.x;
    int row0 = blockIdx.x * 64;
    int row1 = min(row0 + 64, Nn);
    const float* x = g_agg[r];
    double s = 0.0, s2 = 0.0;
    for (int rr = row0; rr < row1; rr++) {
        float v = x[(size_t)rr * D + j];
        s += v; s2 += (double)v * v;
    }
    atomicAdd(&g_sum[r][j], s);
    atomicAdd(&g_sumsq[r][j], s2);
}

__global__ void k_bn_final(const float* __restrict__ gamma, const float* __restrict__ beta, int Nn) {
    int t = threadIdx.x;   // 512
    int r = t >> 7, j = t & 127;
    double mean = g_sum[r][j] / Nn;
    double var = g_sumsq[r][j] / Nn - mean * mean;
    float sc = gamma[j] * (float)(1.0 / sqrt(var + 1e-5));
    g_scale[r][j] = sc;
    g_shift[r][j] = beta[j] - (float)mean * sc;
}

__global__ void k_bn_apply(int Nn) {   // grid (gElem, 4) x 256
    int r = blockIdx.y;
    size_t idx = (size_t)blockIdx.x * blockDim.x + threadIdx.x;
    if (idx >= (size_t)Nn * D) return;
    int j = (int)(idx & 127);
    float v = g_agg[r][idx] * g_scale[r][j] + g_shift[r][j];
    v = v > 0.0f ? v : 0.01f * v;
    g_emb[r][idx] += v;
}

// ---------------- rels update ----------------
__global__ void k_rels_update(const float* __restrict__ Wrt, const float* __restrict__ brt) {
    __shared__ float cur[4 * D];
    int t = threadIdx.x;  // 512
    cur[t] = ((float*)g_rels)[t];
    __syncthreads();
    int r = t >> 7, j = t & 127;
    float s = brt[j];
    #pragma unroll 8
    for (int k = 0; k < D; k++) s = fmaf(cur[r * D + k], Wrt[j * D + k], s);
    ((float*)g_rels)[t] = s;
}

// ---------------- attention ----------------
__global__ void k_attn(int Nn) {
    int gw = (blockIdx.x * blockDim.x + threadIdx.x) >> 5;
    int lane = threadIdx.x & 31;
    if (gw >= Nn * 4) return;
    int n = gw >> 2, h = gw & 3;
    float q[4], kk[4], v[4];
    #pragma unroll
    for (int l = 0; l < 4; l++) {
        const float* base = g_qkv[l] + (size_t)n * 384 + h * 32 + lane;
        q[l]  = base[0] * 0.17677669529663687f;
        kk[l] = base[128];
        v[l]  = base[256];
    }
    float sc[4][4];
    #pragma unroll
    for (int l = 0; l < 4; l++)
        #pragma unroll
        for (int m = 0; m < 4; m++) {
            float p = q[l] * kk[m];
            p += __shfl_xor_sync(0xFFFFFFFFu, p, 16);
            p += __shfl_xor_sync(0xFFFFFFFFu, p, 8);
            p += __shfl_xor_sync(0xFFFFFFFFu, p, 4);
            p += __shfl_xor_sync(0xFFFFFFFFu, p, 2);
            p += __shfl_xor_sync(0xFFFFFFFFu, p, 1);
            sc[l][m] = p;
        }
    #pragma unroll
    for (int l = 0; l < 4; l++) {
        float mx = fmaxf(fmaxf(sc[l][0], sc[l][1]), fmaxf(sc[l][2], sc[l][3]));
        float e0 = expf(sc[l][0] - mx), e1 = expf(sc[l][1] - mx);
        float e2 = expf(sc[l][2] - mx), e3 = expf(sc[l][3] - mx);
        float inv = 1.0f / (e0 + e1 + e2 + e3);
        float o = (e0 * v[0] + e1 * v[1] + e2 * v[2] + e3 * v[3]) * inv;
        g_h[l][(size_t)n * D + h * 32 + lane] = o;
    }
}

// ---------------- coef ----------------
__global__ void k_coef(int Nn) {
    double sv[4] = { g_scores[0] / Nn, g_scores[1] / Nn, g_scores[3] / Nn, g_scores[2] / Nn };
    double mx = sv[0];
    for (int i = 1; i < 4; i++) mx = sv[i] > mx ? sv[i] : mx;
    double e[4], ss = 0.0;
    for (int i = 0; i < 4; i++) { e[i] = exp(sv[i] - mx); ss += e[i]; }
    double w[4];
    for (int i = 0; i < 4; i++) w[i] = e[i] / ss;
    g_coef[0] = (float)w[0];
    g_coef[1] = (float)w[1];
    g_coef[2] = (float)w[3];
    g_coef[3] = (float)w[2];
}

// ---------------- final outputs ----------------
__global__ void k_final(float* __restrict__ out, int Nn) {
    size_t idx = (size_t)blockIdx.x * blockDim.x + threadIdx.x;
    size_t ND = (size_t)Nn * D;
    if (idx >= ND) return;
    int j = (int)(idx & 127);
    float r = g_coef[0] * g_emb[0][idx] + g_coef[1] * g_emb[1][idx]
            + g_coef[2] * g_emb[2][idx] + g_coef[3] * g_emb[3][idx];
    out[idx]          = r;
    out[ND + idx]     = r * g_rels[3][j];
    out[2 * ND + idx] = r * g_rels[0][j];
    out[3 * ND + idx] = r * g_rels[1][j];
    out[4 * ND + idx] = r * g_rels[2][j];
}

// ---------------- host orchestration ----------------
extern "C" void kernel_launch(void* const* d_in, const int* in_sizes, int n_in,
                              void* d_out, int out_size) {
    const float* features   = (const float*)d_in[0];
    const float* rel_emb    = (const float*)d_in[1];
    const int*   edge_index = (const int*)  d_in[2];
    const float* W_gcn      = (const float*)d_in[3];
    const float* b_gcn      = (const float*)d_in[4];
    const float* bn_gamma   = (const float*)d_in[5];
    const float* bn_beta    = (const float*)d_in[6];
    const float* W_rt       = (const float*)d_in[7];
    const float* b_rt       = (const float*)d_in[8];
    const float* attn_w_in  = (const float*)d_in[9];
    const float* attn_b_in  = (const float*)d_in[10];
    const float* attn_w_out = (const float*)d_in[11];
    const float* attn_b_out = (const float*)d_in[12];
    const float* alphas     = (const float*)d_in[13];
    const float* fusion_q   = (const float*)d_in[14];
    const float* fusion_w   = (const float*)d_in[15];
    const float* fusion_b   = (const float*)d_in[16];

    int Nn = in_sizes[0] / D;
    int E  = in_sizes[2] / 8;
    if (Nn > MAXN || E > EMAX) return;

    static float *emb = nullptr, *h, *agg, *qkv, *rels;
    static double *scores;
    static bool attr_done = false;
    if (!emb) {
        cudaGetSymbolAddress((void**)&emb,    g_emb);
        cudaGetSymbolAddress((void**)&h,      g_h);
        cudaGetSymbolAddress((void**)&agg,    g_agg);
        cudaGetSymbolAddress((void**)&qkv,    g_qkv);
        cudaGetSymbolAddress((void**)&rels,   g_rels);
        cudaGetSymbolAddress((void**)&scores, g_scores);
    }
    const int SMEM_T  = 73728;   // TRANSB variants
    const int SMEM_NT = 71680;   // !TRANSB variant
    if (!attr_done) {
        cudaFuncSetAttribute((const void*)k_gemm_tf32<false, true,  false, 0>,
                             cudaFuncAttributeMaxDynamicSharedMemorySize, SMEM_NT);
        cudaFuncSetAttribute((const void*)k_gemm_tf32<true,  false, true,  0>,
                             cudaFuncAttributeMaxDynamicSharedMemorySize, SMEM_T);
        cudaFuncSetAttribute((const void*)k_gemm_tf32<true,  false, true,  1>,
                             cudaFuncAttributeMaxDynamicSharedMemorySize, SMEM_T);
        cudaFuncSetAttribute((const void*)k_gemm_tf32<true,  false, true,  2>,
                             cudaFuncAttributeMaxDynamicSharedMemorySize, SMEM_T);
        attr_done = true;
    }

    const long S = (long)MAXN * D;
    const long Q = (long)MAXN * 384;
    const long4 ident = make_long4(0, S, 2 * S, 3 * S);
    const long4 smapo = make_long4(3 * S, 0, 2 * S, 1 * S);  // stack order -> processing order
    const long4 qoff  = make_long4(0, Q, 2 * Q, 3 * Q);
    const long4 zero4 = make_long4(0, 0, 0, 0);

    size_t ND = (size_t)Nn * D;
    int gElem = (int)((ND + TPB - 1) / TPB);
    int gEdge = (E + TPB - 1) / TPB;
    int gy    = (Nn + 127) / 128;
    int nb    = (Nn + 1023) / 1024;
    int gAgg  = (int)(((size_t)Nn * 32 + TPB - 1) / TPB);
    int gTail = (int)(((size_t)(MAXN - Nn) * D + TPB - 1) / TPB);

    k_init<<<gElem, TPB>>>(features, rel_emb, Nn);
    if (gTail > 0) k_zero_tail<<<gTail, TPB>>>(Nn);
    k_hist<<<dim3(gEdge, 4), TPB>>>(edge_index, E);
    k_dinv<<<(4 * Nn + TPB - 1) / TPB, TPB>>>(Nn);
    k_scan1<<<dim3(nb, 4), 1024>>>(Nn);
    k_scan2<<<4, 64>>>(nb);
    k_scan3<<<dim3(nb, 4), 1024>>>(Nn);
    k_fill<<<dim3(gEdge, 4), TPB>>>(edge_index, E);

    for (int i = 0; i < 3; i++) {
        const float* Wg = W_gcn + (size_t)i * D * D;
        const float* bg = b_gcn + (size_t)i * D;
        // h[r] = (emb[r] * rels[r]) @ Wg   (batched over r)
        k_gemm_tf32<false, true, false, 0><<<dim3(1, gy, 4), 256, SMEM_NT>>>(
            emb, ident, Wg, h, ident, Nn, D, D, rels, nullptr, nullptr, zero4, nullptr, nullptr);
        // agg[r] = self-loop + bias + CSR gather
        k_agg<<<dim3(gAgg, 4), TPB>>>(bg, Nn);
        if (i < 2) {
            k_bn_zero<<<1, 512>>>();
            k_bn_stats<<<dim3((Nn + 63) / 64, 4), 128>>>(Nn);
            k_bn_final<<<1, 512>>>(bn_gamma + (size_t)i * D, bn_beta + (size_t)i * D, Nn);
            k_bn_apply<<<dim3(gElem, 4), TPB>>>(Nn);
        }
        k_rels_update<<<1, 512>>>(W_rt + (size_t)i * D * D, b_rt + (size_t)i * D);
    }

    // QKV over stk[l] = agg[SMAP[l]]
    k_gemm_tf32<true, false, true, 0><<<dim3(3, gy, 4), 256, SMEM_T>>>(
        agg, smapo, attn_w_in, qkv, qoff, Nn, 384, D,
        nullptr, attn_b_in, nullptr, zero4, nullptr, nullptr);
    k_attn<<<(int)(((size_t)Nn * 128 + TPB - 1) / TPB), TPB>>>(Nn);
    // out-proj + fused blend -> emb[l]
    k_gemm_tf32<true, false, true, 1><<<dim3(1, gy, 4), 256, SMEM_T>>>(
        h, ident, attn_w_out, emb, ident, Nn, D, D,
        nullptr, attn_b_out, agg, smapo, alphas, nullptr);
    // fused score GEMMs
    k_gemm_tf32<true, false, true, 2><<<dim3(1, gy, 4), 256, SMEM_T>>>(
        emb, ident, fusion_w, h, ident, Nn, D, D,
        nullptr, fusion_b, fusion_q, zero4, nullptr, scores);
    k_coef<<<1, 1>>>(Nn);
    k_final<<<gElem, TPB>>>((float*)d_out, Nn);
}

// round 9
// speedup vs baseline: 2.8435x; 1.0107x over previous
#include <cuda_runtime.h>
#include <math.h>
#include <stdint.h>

#define D 128
#define MAXN 50048           // 391 * 128, multiple of 128
#define EMAX 409600
#define TPB 256

// ---------------- scratch (static device globals; no allocations) ----------------
__device__ __align__(16) float g_emb[4][(size_t)MAXN * D];
__device__ __align__(16) float g_h  [4][(size_t)MAXN * D];
__device__ __align__(16) float g_agg[4][(size_t)MAXN * D];
__device__ __align__(16) float g_qkv[4][(size_t)MAXN * 384];
__device__ int   g_cnt   [4][MAXN];
__device__ int   g_rowptr[4][MAXN + 1];
__device__ int   g_wofs  [4][MAXN];
__device__ int   g_psum  [4][64];
__device__ int   g_total [4];
__device__ int   g_csr_src[4][EMAX];
__device__ float g_csr_c [4][EMAX];
__device__ __align__(16) float g_dinv[4][MAXN];
__device__ __align__(16) float g_rels[4][D];
__device__ double g_sum[4][D];
__device__ double g_sumsq[4][D];
__device__ float  g_scale[4][D];
__device__ float  g_shift[4][D];
__device__ double g_scores[4];
__device__ float  g_coef[4];

// ---------------- helpers ----------------
__device__ __forceinline__ uint32_t f2tf(float x) {
    uint32_t u;
    asm("cvt.rna.tf32.f32 %0, %1;" : "=r"(u) : "f"(x));
    return u;
}
__device__ __forceinline__ void mma_tf32(float* c, const uint32_t* a, const uint32_t* b) {
    asm volatile(
        "mma.sync.aligned.m16n8k8.row.col.f32.tf32.tf32.f32 "
        "{%0,%1,%2,%3}, {%4,%5,%6,%7}, {%8,%9}, {%0,%1,%2,%3};"
        : "+f"(c[0]), "+f"(c[1]), "+f"(c[2]), "+f"(c[3])
        : "r"(a[0]), "r"(a[1]), "r"(a[2]), "r"(a[3]), "r"(b[0]), "r"(b[1]));
}
__device__ __forceinline__ void cp16(uint32_t dst, const void* src) {
    asm volatile("cp.async.cg.shared.global [%0], [%1], 16;" :: "r"(dst), "l"(src));
}

// ---------------- init: emb[0] = features; permute rels; zero counters/scores ----
__global__ void k_init(const float* __restrict__ feat, const float* __restrict__ rel_emb, int Nn) {
    size_t idx = (size_t)blockIdx.x * blockDim.x + threadIdx.x;
    size_t tot = (size_t)Nn * D;
    if (idx < tot) {
        g_emb[0][idx] = feat[idx];
    }
    if (idx < 4 * (size_t)MAXN) ((int*)g_cnt)[idx] = 0;
    if (idx < 4 * D) {
        const int perm[4] = {3, 0, 1, 2};
        int r = (int)(idx / D), j = (int)(idx % D);
        g_rels[r][j] = rel_emb[perm[r] * D + j];
    }
    if (idx < 4) g_scores[idx] = 0.0;
}

// zero scratch tail rows [Nn, MAXN) so GEMM A-loads need no bounds checks
__global__ void k_zero_tail(int Nn) {
    size_t tail = (size_t)(MAXN - Nn) * D;
    size_t idx = (size_t)blockIdx.x * blockDim.x + threadIdx.x;
    if (idx >= tail) return;
    size_t o = (size_t)Nn * D + idx;
    #pragma unroll
    for (int r = 0; r < 4; r++) { g_emb[r][o] = 0.f; g_h[r][o] = 0.f; g_agg[r][o] = 0.f; }
}

// ---------------- CSR build ----------------
__global__ void k_hist(const int* __restrict__ edge, int E) {
    const int perm[4] = {3, 0, 1, 2};
    int r = blockIdx.y;
    const int* dst = edge + ((size_t)perm[r] * 2 + 1) * E;
    int t = blockIdx.x * blockDim.x + threadIdx.x;
    if (t < E) atomicAdd(&g_cnt[r][dst[t]], 1);
}

__global__ void k_dinv(int Nn) {
    int idx = blockIdx.x * blockDim.x + threadIdx.x;
    if (idx < 4 * Nn) {
        int r = idx / Nn, n = idx % Nn;
        g_dinv[r][n] = rsqrtf((float)g_cnt[r][n] + 1.0f);
    }
}

__global__ void k_scan1(int Nn) {     // grid (nb, 4) x 1024
    int r = blockIdx.y, t = threadIdx.x;
    int i = blockIdx.x * 1024 + t;
    int v = (i < Nn) ? g_cnt[r][i] : 0;
    int x = v;
    #pragma unroll
    for (int o = 1; o < 32; o <<= 1) {
        int y = __shfl_up_sync(0xFFFFFFFFu, x, o);
        if ((t & 31) >= o) x += y;
    }
    __shared__ int ws[32];
    if ((t & 31) == 31) ws[t >> 5] = x;
    __syncthreads();
    if (t < 32) {
        int y = ws[t];
        #pragma unroll
        for (int o = 1; o < 32; o <<= 1) {
            int z = __shfl_up_sync(0xFFFFFFFFu, y, o);
            if (t >= o) y += z;
        }
        ws[t] = y;
    }
    __syncthreads();
    int off = (t >= 32) ? ws[(t >> 5) - 1] : 0;
    int incl = x + off;
    if (i < Nn) g_rowptr[r][i] = incl - v;
    if (t == 1023) g_psum[r][blockIdx.x] = incl;
}

__global__ void k_scan2(int nb) {     // grid 4 x 64
    int r = blockIdx.x, t = threadIdx.x;
    int v = (t < nb) ? g_psum[r][t] : 0;
    int x = v;
    #pragma unroll
    for (int o = 1; o < 32; o <<= 1) {
        int y = __shfl_up_sync(0xFFFFFFFFu, x, o);
        if ((t & 31) >= o) x += y;
    }
    __shared__ int w2[2];
    if ((t & 31) == 31) w2[t >> 5] = x;
    __syncthreads();
    int off = (t >= 32) ? w2[0] : 0;
    int incl = x + off;
    g_psum[r][t] = incl - v;
    if (t == 63) g_total[r] = incl;
}

__global__ void k_scan3(int Nn) {     // grid (nb, 4) x 1024
    int r = blockIdx.y;
    int i = blockIdx.x * 1024 + threadIdx.x;
    if (i < Nn) {
        int val = g_rowptr[r][i] + g_psum[r][blockIdx.x];
        g_rowptr[r][i] = val;
        g_wofs[r][i] = val;
    }
    if (i == 0) g_rowptr[r][Nn] = g_total[r];
}

__global__ void k_fill(const int* __restrict__ edge, int E) {
    const int perm[4] = {3, 0, 1, 2};
    int r = blockIdx.y;
    const int* src = edge + ((size_t)perm[r] * 2) * E;
    const int* dst = src + E;
    int e = blockIdx.x * blockDim.x + threadIdx.x;
    if (e >= E) return;
    int s = src[e], d = dst[e];
    int pos = atomicAdd(&g_wofs[r][d], 1);
    g_csr_src[r][pos] = s;
    g_csr_c[r][pos] = g_dinv[r][s] * g_dinv[r][d];
}

// ---------------- batched pipelined TF32 GEMM ----------------
// BM=128 BN=128 BK=32, 256 threads, cp.async 2-stage double buffer.
// z = blockIdx.z selects batch slice via long4 offsets.
// EPI: 0 plain store (+bias), 1 blend (C = (acc+bias)*alpha[z] + (1-alpha)*stk),
//      2 score (no store; sum lrelu(acc+bias)*q -> scores[z]).
template <bool TRANSB, bool SCALE_A, bool BIAS, int EPI>
__global__ void __launch_bounds__(256) k_gemm_tf32(
    const float* __restrict__ A_base, long4 a_off,
    const float* __restrict__ Bm,
    float* __restrict__ C_base, long4 c_off,
    int M, int N, int K,
    const float* __restrict__ cs_base,
    const float* __restrict__ bias,
    const float* __restrict__ ep_base, long4 ep_off,
    const float* __restrict__ alphas,
    double* __restrict__ scores)
{
    extern __shared__ uint32_t sm[];
    __shared__ float s_cs[128];
    const int tid = threadIdx.x;
    const int lane = tid & 31, wid = tid >> 5;
    const int z = blockIdx.z;
    const long ao = (z == 0) ? a_off.x : (z == 1) ? a_off.y : (z == 2) ? a_off.z : a_off.w;
    const long co = (z == 0) ? c_off.x : (z == 1) ? c_off.y : (z == 2) ? c_off.z : c_off.w;
    const long eo = (z == 0) ? ep_off.x : (z == 1) ? ep_off.y : (z == 2) ? ep_off.z : ep_off.w;
    const float* A = A_base + ao;
    float* C = C_base + co;
    const int bm = blockIdx.y * 128;
    const int bn = blockIdx.x * 128;
    const int warp_m = (wid & 3) * 32;
    const int warp_n = (wid >> 2) * 64;
    const uint32_t smem_u = (uint32_t)__cvta_generic_to_shared(sm);

    if (SCALE_A && tid < 128) s_cs[tid] = cs_base[z * 128 + tid];

    float acc[2][8][4];
    #pragma unroll
    for (int i = 0; i < 2; i++)
        #pragma unroll
        for (int j = 0; j < 8; j++)
            #pragma unroll
            for (int q = 0; q < 4; q++) acc[i][j][q] = 0.0f;

    auto load_stage = [&](int st, int k0) {
        #pragma unroll
        for (int i = 0; i < 4; i++) {
            int id = tid + i * 256;
            int m = id >> 3, c = id & 7;
            cp16(smem_u + (uint32_t)(st * 4608 + m * 36 + c * 4) * 4,
                 A + (size_t)(bm + m) * K + k0 + c * 4);
        }
        if (TRANSB) {
            #pragma unroll
            for (int i = 0; i < 4; i++) {
                int id = tid + i * 256;
                int n = id >> 3, c = id & 7;
                cp16(smem_u + (uint32_t)(9216 + st * 4608 + n * 36 + c * 4) * 4,
                     Bm + (size_t)(bn + n) * K + k0 + c * 4);
            }
        } else {
            #pragma unroll
            for (int i = 0; i < 4; i++) {
                int id = tid + i * 256;
                int k = id >> 5, c = id & 31;
                cp16(smem_u + (uint32_t)(9216 + st * 4352 + k * 136 + c * 4) * 4,
                     Bm + (size_t)(k0 + k) * N + bn + c * 4);
            }
        }
    };

    const int r0 = lane >> 2, c0 = lane & 3;
    const int nk = K >> 5;

    load_stage(0, 0);
    asm volatile("cp.async.commit_group;");

    for (int kt = 0; kt < nk; kt++) {
        const int cur = kt & 1;
        const int k0g = kt << 5;
        if (kt + 1 < nk) {
            load_stage((kt + 1) & 1, (kt + 1) << 5);
            asm volatile("cp.async.commit_group;");
            asm volatile("cp.async.wait_group 1;");
        } else {
            asm volatile("cp.async.wait_group 0;");
        }
        __syncthreads();

        #pragma unroll
        for (int ks = 0; ks < 32; ks += 8) {
            uint32_t a[2][4], b[8][2];
            float cs0 = 1.0f, cs1 = 1.0f;
            if (SCALE_A) { cs0 = s_cs[k0g + ks + c0]; cs1 = s_cs[k0g + ks + 4 + c0]; }
            #pragma unroll
            for (int fm = 0; fm < 2; fm++) {
                int mb = warp_m + fm * 16;
                const uint32_t* Ab = sm + cur * 4608;
                float v0 = __uint_as_float(Ab[(mb + r0) * 36 + ks + c0]);
                float v1 = __uint_as_float(Ab[(mb + 8 + r0) * 36 + ks + c0]);
                float v2 = __uint_as_float(Ab[(mb + r0) * 36 + ks + 4 + c0]);
                float v3 = __uint_as_float(Ab[(mb + 8 + r0) * 36 + ks + 4 + c0]);
                if (SCALE_A) { v0 *= cs0; v1 *= cs0; v2 *= cs1; v3 *= cs1; }
                a[fm][0] = f2tf(v0); a[fm][1] = f2tf(v1);
                a[fm][2] = f2tf(v2); a[fm][3] = f2tf(v3);
            }
            if (TRANSB) {
                const uint32_t* Bb = sm + 9216 + cur * 4608;
                #pragma unroll
                for (int fn = 0; fn < 8; fn++) {
                    int nb = warp_n + fn * 8 + r0;
                    b[fn][0] = f2tf(__uint_as_float(Bb[nb * 36 + ks + c0]));
                    b[fn][1] = f2tf(__uint_as_float(Bb[nb * 36 + ks + 4 + c0]));
                }
            } else {
                const uint32_t* Bb = sm + 9216 + cur * 4352;
                #pragma unroll
                for (int fn = 0; fn < 8; fn++) {
                    int nb = warp_n + fn * 8 + r0;
                    b[fn][0] = f2tf(__uint_as_float(Bb[(ks + c0) * 136 + nb]));
                    b[fn][1] = f2tf(__uint_as_float(Bb[(ks + 4 + c0) * 136 + nb]));
                }
            }
            #pragma unroll
            for (int fm = 0; fm < 2; fm++)
                #pragma unroll
                for (int fn = 0; fn < 8; fn++)
                    mma_tf32(acc[fm][fn], a[fm], b[fn]);
        }
        __syncthreads();
    }

    // ---- epilogue ----
    const int cc = (lane & 3) * 2;
    float alpha = 0.f, oma = 0.f;
    if (EPI == 1) { alpha = alphas[z]; oma = 1.0f - alpha; }
    const float* EP = (EPI != 0) ? (ep_base + (EPI == 1 ? eo : 0)) : nullptr;
    float score_local = 0.0f;

    #pragma unroll
    for (int fm = 0; fm < 2; fm++) {
        #pragma unroll
        for (int fn = 0; fn < 8; fn++) {
            int row = bm + warp_m + fm * 16 + r0;
            int col = bn + warp_n + fn * 8 + cc;
            float b0 = BIAS ? bias[col] : 0.0f;
            float b1 = BIAS ? bias[col + 1] : 0.0f;
            float v00 = acc[fm][fn][0] + b0, v01 = acc[fm][fn][1] + b1;
            float v10 = acc[fm][fn][2] + b0, v11 = acc[fm][fn][3] + b1;
            if (EPI == 0) {
                if (row < M)     *(float2*)(C + (size_t)row * N + col)       = make_float2(v00, v01);
                if (row + 8 < M) *(float2*)(C + (size_t)(row + 8) * N + col) = make_float2(v10, v11);
            } else if (EPI == 1) {
                if (row < M) {
                    float2 s = *(const float2*)(EP + (size_t)row * N + col);
                    *(float2*)(C + (size_t)row * N + col) =
                        make_float2(v00 * alpha + oma * s.x, v01 * alpha + oma * s.y);
                }
                if (row + 8 < M) {
                    float2 s = *(const float2*)(EP + (size_t)(row + 8) * N + col);
                    *(float2*)(C + (size_t)(row + 8) * N + col) =
                        make_float2(v10 * alpha + oma * s.x, v11 * alpha + oma * s.y);
                }
            } else {
                float q0 = EP[col], q1 = EP[col + 1];
                if (row < M) {
                    float l0 = v00 > 0.f ? v00 : 0.01f * v00;
                    float l1 = v01 > 0.f ? v01 : 0.01f * v01;
                    score_local += l0 * q0 + l1 * q1;
                }
                if (row + 8 < M) {
                    float l0 = v10 > 0.f ? v10 : 0.01f * v10;
                    float l1 = v11 > 0.f ? v11 : 0.01f * v11;
                    score_local += l0 * q0 + l1 * q1;
                }
            }
        }
    }

    if (EPI == 2) {
        __shared__ float sred[8];
        #pragma unroll
        for (int o = 16; o > 0; o >>= 1)
            score_local += __shfl_xor_sync(0xFFFFFFFFu, score_local, o);
        if (lane == 0) sred[wid] = score_local;
        __syncthreads();
        if (tid == 0) {
            float tot = 0.f;
            #pragma unroll
            for (int w = 0; w < 8; w++) tot += sred[w];
            atomicAdd(&scores[z], (double)tot);
        }
    }
}

// ---------------- CSR aggregation (batched, warp per dst; 4-way unrolled) ----------------
__global__ void k_agg(const float* __restrict__ bias, int Nn) {
    int r = blockIdx.y;
    int gw = (blockIdx.x * blockDim.x + threadIdx.x) >> 5;
    int lane = threadIdx.x & 31;
    if (gw >= Nn) return;
    const float* h = g_h[r];
    const int* csr_src = g_csr_src[r];
    const float* csr_c = g_csr_c[r];
    float di = g_dinv[r][gw];
    float d2 = di * di;
    float4 acc = ((const float4*)(h + (size_t)gw * D))[lane];
    float4 bv  = ((const float4*)bias)[lane];
    acc.x = acc.x * d2 + bv.x;
    acc.y = acc.y * d2 + bv.y;
    acc.z = acc.z * d2 + bv.z;
    acc.w = acc.w * d2 + bv.w;
    int beg = g_rowptr[r][gw], end = g_rowptr[r][gw + 1];
    int e = beg;
    int end4 = beg + ((end - beg) & ~3);
    for (; e < end4; e += 4) {
        int sA = csr_src[e], sB = csr_src[e + 1], sC = csr_src[e + 2], sD = csr_src[e + 3];
        float cA = csr_c[e], cB = csr_c[e + 1], cC = csr_c[e + 2], cD = csr_c[e + 3];
        float4 hA = ((const float4*)(h + (size_t)sA * D))[lane];
        float4 hB = ((const float4*)(h + (size_t)sB * D))[lane];
        float4 hC = ((const float4*)(h + (size_t)sC * D))[lane];
        float4 hD = ((const float4*)(h + (size_t)sD * D))[lane];
        acc.x += hA.x * cA + hB.x * cB + hC.x * cC + hD.x * cD;
        acc.y += hA.y * cA + hB.y * cB + hC.y * cC + hD.y * cD;
        acc.z += hA.z * cA + hB.z * cB + hC.z * cC + hD.z * cD;
        acc.w += hA.w * cA + hB.w * cB + hC.w * cC + hD.w * cD;
    }
    for (; e < end; e++) {
        int s = csr_src[e];
        float c = csr_c[e];
        float4 hv = ((const float4*)(h + (size_t)s * D))[lane];
        acc.x += hv.x * c;
        acc.y += hv.y * c;
        acc.z += hv.z * c;
        acc.w += hv.w * c;
    }
    ((float4*)(g_agg[r] + (size_t)gw * D))[lane] = acc;
}

// ---------------- BatchNorm (batched over relations) ----------------
__global__ void k_bn_zero() {
    int t = threadIdx.x;   // 512
    ((double*)g_sum)[t] = 0.0;
    ((double*)g_sumsq)[t] = 0.0;
}

__global__ void k_bn_stats(int Nn) {   // grid (nb, 4) x 128
    int r = blockIdx.y;
    int j = threadIdx.x;
    int row0 = blockIdx.x * 64;
    int row1 = min(row0 + 64, Nn);
    const float* x = g_agg[r];
    double s = 0.0, s2 = 0.0;
    for (int rr = row0; rr < row1; rr++) {
        float v = x[(size_t)rr * D + j];
        s += v; s2 += (double)v * v;
    }
    atomicAdd(&g_sum[r][j], s);
    atomicAdd(&g_sumsq[r][j], s2);
}

__global__ void k_bn_final(const float* __restrict__ gamma, const float* __restrict__ beta, int Nn) {
    int t = threadIdx.x;   // 512
    int r = t >> 7, j = t & 127;
    double mean = g_sum[r][j] / Nn;
    double var = g_sumsq[r][j] / Nn - mean * mean;
    float sc = gamma[j] * (float)(1.0 / sqrt(var + 1e-5));
    g_scale[r][j] = sc;
    g_shift[r][j] = beta[j] - (float)mean * sc;
}

// emb[r] = base + lrelu(agg*scale+shift); base = features (layer0) or emb[r]
__global__ void k_bn_apply(const float* __restrict__ base, int Nn) {   // grid (gElem, 4) x 256
    int r = blockIdx.y;
    size_t idx = (size_t)blockIdx.x * blockDim.x + threadIdx.x;
    if (idx >= (size_t)Nn * D) return;
    int j = (int)(idx & 127);
    float v = g_agg[r][idx] * g_scale[r][j] + g_shift[r][j];
    v = v > 0.0f ? v : 0.01f * v;
    float b = base ? base[idx] : g_emb[r][idx];
    g_emb[r][idx] = b + v;
}

// ---------------- rels update ----------------
__global__ void k_rels_update(const float* __restrict__ Wrt, const float* __restrict__ brt) {
    __shared__ float cur[4 * D];
    int t = threadIdx.x;  // 512
    cur[t] = ((float*)g_rels)[t];
    __syncthreads();
    int r = t >> 7, j = t & 127;
    float s = brt[j];
    #pragma unroll 8
    for (int k = 0; k < D; k++) s = fmaf(cur[r * D + k], Wrt[j * D + k], s);
    ((float*)g_rels)[t] = s;
}

// ---------------- attention ----------------
__global__ void k_attn(int Nn) {
    int gw = (blockIdx.x * blockDim.x + threadIdx.x) >> 5;
    int lane = threadIdx.x & 31;
    if (gw >= Nn * 4) return;
    int n = gw >> 2, h = gw & 3;
    float q[4], kk[4], v[4];
    #pragma unroll
    for (int l = 0; l < 4; l++) {
        const float* base = g_qkv[l] + (size_t)n * 384 + h * 32 + lane;
        q[l]  = base[0] * 0.17677669529663687f;
        kk[l] = base[128];
        v[l]  = base[256];
    }
    float sc[4][4];
    #pragma unroll
    for (int l = 0; l < 4; l++)
        #pragma unroll
        for (int m = 0; m < 4; m++) {
            float p = q[l] * kk[m];
            p += __shfl_xor_sync(0xFFFFFFFFu, p, 16);
            p += __shfl_xor_sync(0xFFFFFFFFu, p, 8);
            p += __shfl_xor_sync(0xFFFFFFFFu, p, 4);
            p += __shfl_xor_sync(0xFFFFFFFFu, p, 2);
            p += __shfl_xor_sync(0xFFFFFFFFu, p, 1);
            sc[l][m] = p;
        }
    #pragma unroll
    for (int l = 0; l < 4; l++) {
        float mx = fmaxf(fmaxf(sc[l][0], sc[l][1]), fmaxf(sc[l][2], sc[l][3]));
        float e0 = expf(sc[l][0] - mx), e1 = expf(sc[l][1] - mx);
        float e2 = expf(sc[l][2] - mx), e3 = expf(sc[l][3] - mx);
        float inv = 1.0f / (e0 + e1 + e2 + e3);
        float o = (e0 * v[0] + e1 * v[1] + e2 * v[2] + e3 * v[3]) * inv;
        g_h[l][(size_t)n * D + h * 32 + lane] = o;
    }
}

// ---------------- coef ----------------
__global__ void k_coef(int Nn) {
    double sv[4] = { g_scores[0] / Nn, g_scores[1] / Nn, g_scores[3] / Nn, g_scores[2] / Nn };
    double mx = sv[0];
    for (int i = 1; i < 4; i++) mx = sv[i] > mx ? sv[i] : mx;
    double e[4], ss = 0.0;
    for (int i = 0; i < 4; i++) { e[i] = exp(sv[i] - mx); ss += e[i]; }
    double w[4];
    for (int i = 0; i < 4; i++) w[i] = e[i] / ss;
    g_coef[0] = (float)w[0];
    g_coef[1] = (float)w[1];
    g_coef[2] = (float)w[3];
    g_coef[3] = (float)w[2];
}

// ---------------- final outputs ----------------
__global__ void k_final(float* __restrict__ out, int Nn) {
    size_t idx = (size_t)blockIdx.x * blockDim.x + threadIdx.x;
    size_t ND = (size_t)Nn * D;
    if (idx >= ND) return;
    int j = (int)(idx & 127);
    float r = g_coef[0] * g_emb[0][idx] + g_coef[1] * g_emb[1][idx]
            + g_coef[2] * g_emb[2][idx] + g_coef[3] * g_emb[3][idx];
    out[idx]          = r;
    out[ND + idx]     = r * g_rels[3][j];
    out[2 * ND + idx] = r * g_rels[0][j];
    out[3 * ND + idx] = r * g_rels[1][j];
    out[4 * ND + idx] = r * g_rels[2][j];
}

// ---------------- host orchestration ----------------
extern "C" void kernel_launch(void* const* d_in, const int* in_sizes, int n_in,
                              void* d_out, int out_size) {
    const float* features   = (const float*)d_in[0];
    const float* rel_emb    = (const float*)d_in[1];
    const int*   edge_index = (const int*)  d_in[2];
    const float* W_gcn      = (const float*)d_in[3];
    const float* b_gcn      = (const float*)d_in[4];
    const float* bn_gamma   = (const float*)d_in[5];
    const float* bn_beta    = (const float*)d_in[6];
    const float* W_rt       = (const float*)d_in[7];
    const float* b_rt       = (const float*)d_in[8];
    const float* attn_w_in  = (const float*)d_in[9];
    const float* attn_b_in  = (const float*)d_in[10];
    const float* attn_w_out = (const float*)d_in[11];
    const float* attn_b_out = (const float*)d_in[12];
    const float* alphas     = (const float*)d_in[13];
    const float* fusion_q   = (const float*)d_in[14];
    const float* fusion_w   = (const float*)d_in[15];
    const float* fusion_b   = (const float*)d_in[16];

    int Nn = in_sizes[0] / D;
    int E  = in_sizes[2] / 8;
    if (Nn > MAXN || E > EMAX) return;

    static float *emb = nullptr, *h, *agg, *qkv, *rels;
    static double *scores;
    static bool attr_done = false;
    if (!emb) {
        cudaGetSymbolAddress((void**)&emb,    g_emb);
        cudaGetSymbolAddress((void**)&h,      g_h);
        cudaGetSymbolAddress((void**)&agg,    g_agg);
        cudaGetSymbolAddress((void**)&qkv,    g_qkv);
        cudaGetSymbolAddress((void**)&rels,   g_rels);
        cudaGetSymbolAddress((void**)&scores, g_scores);
    }
    const int SMEM_T  = 73728;
    const int SMEM_NT = 71680;
    if (!attr_done) {
        cudaFuncSetAttribute((const void*)k_gemm_tf32<false, true,  false, 0>,
                             cudaFuncAttributeMaxDynamicSharedMemorySize, SMEM_NT);
        cudaFuncSetAttribute((const void*)k_gemm_tf32<true,  false, true,  0>,
                             cudaFuncAttributeMaxDynamicSharedMemorySize, SMEM_T);
        cudaFuncSetAttribute((const void*)k_gemm_tf32<true,  false, true,  1>,
                             cudaFuncAttributeMaxDynamicSharedMemorySize, SMEM_T);
        cudaFuncSetAttribute((const void*)k_gemm_tf32<true,  false, true,  2>,
                             cudaFuncAttributeMaxDynamicSharedMemorySize, SMEM_T);
        attr_done = true;
    }

    const long S = (long)MAXN * D;
    const long Q = (long)MAXN * 384;
    const long4 ident = make_long4(0, S, 2 * S, 3 * S);
    const long4 smapo = make_long4(3 * S, 0, 2 * S, 1 * S);
    const long4 qoff  = make_long4(0, Q, 2 * Q, 3 * Q);
    const long4 zero4 = make_long4(0, 0, 0, 0);

    size_t ND = (size_t)Nn * D;
    int gElem = (int)((ND + TPB - 1) / TPB);
    int gEdge = (E + TPB - 1) / TPB;
    int gy    = (Nn + 127) / 128;
    int nb    = (Nn + 1023) / 1024;
    int gAgg  = (int)(((size_t)Nn * 32 + TPB - 1) / TPB);
    int gTail = (int)(((size_t)(MAXN - Nn) * D + TPB - 1) / TPB);

    k_init<<<gElem, TPB>>>(features, rel_emb, Nn);
    if (gTail > 0) k_zero_tail<<<gTail, TPB>>>(Nn);
    k_hist<<<dim3(gEdge, 4), TPB>>>(edge_index, E);
    k_dinv<<<(4 * Nn + TPB - 1) / TPB, TPB>>>(Nn);
    k_scan1<<<dim3(nb, 4), 1024>>>(Nn);
    k_scan2<<<4, 64>>>(nb);
    k_scan3<<<dim3(nb, 4), 1024>>>(Nn);
    k_fill<<<dim3(gEdge, 4), TPB>>>(edge_index, E);

    for (int i = 0; i < 3; i++) {
        const float* Wg = W_gcn + (size_t)i * D * D;
        const float* bg = b_gcn + (size_t)i * D;
        // h[r] = (emb_src * rels[r]) @ Wg ; layer 0 reads emb[0] for all r
        k_gemm_tf32<false, true, false, 0><<<dim3(1, gy, 4), 256, SMEM_NT>>>(
            emb, (i == 0) ? zero4 : ident, Wg, h, ident, Nn, D, D,
            rels, nullptr, nullptr, zero4, nullptr, nullptr);
        // agg[r] = self-loop + bias + CSR gather
        k_agg<<<dim3(gAgg, 4), TPB>>>(bg, Nn);
        if (i < 2) {
            k_bn_zero<<<1, 512>>>();
            k_bn_stats<<<dim3((Nn + 63) / 64, 4), 128>>>(Nn);
            k_bn_final<<<1, 512>>>(bn_gamma + (size_t)i * D, bn_beta + (size_t)i * D, Nn);
            k_bn_apply<<<dim3(gElem, 4), TPB>>>((i == 0) ? features : nullptr, Nn);
        }
        // i == 2: final embeddings stay in agg[r]
        k_rels_update<<<1, 512>>>(W_rt + (size_t)i * D * D, b_rt + (size_t)i * D);
    }

    // QKV over stk[l] = agg[SMAP[l]]
    k_gemm_tf32<true, false, true, 0><<<dim3(3, gy, 4), 256, SMEM_T>>>(
        agg, smapo, attn_w_in, qkv, qoff, Nn, 384, D,
        nullptr, attn_b_in, nullptr, zero4, nullptr, nullptr);
    k_attn<<<(int)(((size_t)Nn * 128 + TPB - 1) / TPB), TPB>>>(Nn);
    // out-proj + fused blend -> emb[l]
    k_gemm_tf32<true, false, true, 1><<<dim3(1, gy, 4), 256, SMEM_T>>>(
        h, ident, attn_w_out, emb, ident, Nn, D, D,
        nullptr, attn_b_out, agg, smapo, alphas, nullptr);
    // fused score GEMMs
    k_gemm_tf32<true, false, true, 2><<<dim3(1, gy, 4), 256, SMEM_T>>>(
        emb, ident, fusion_w, h, ident, Nn, D, D,
        nullptr, fusion_b, fusion_q, zero4, nullptr, scores);
    k_coef<<<1, 1>>>(Nn);
    k_final<<<gElem, TPB>>>((float*)d_out, Nn);
}

// round 10
// speedup vs baseline: 2.9619x; 1.0416x over previous
#include <cuda_runtime.h>
#include <math.h>
#include <stdint.h>

#define D 128
#define MAXN 50048           // 391 * 128, multiple of 128
#define EMAX 409600
#define TPB 256

// ---------------- scratch (static device globals; no allocations) ----------------
__device__ __align__(16) float g_emb[4][(size_t)MAXN * D];
__device__ __align__(16) float g_h  [4][(size_t)MAXN * D];
__device__ __align__(16) float g_agg[4][(size_t)MAXN * D];
__device__ __align__(16) float g_qkv[4][(size_t)MAXN * 384];
__device__ int   g_cnt   [4][MAXN];
__device__ int   g_rowptr[4][MAXN + 1];
__device__ int   g_wofs  [4][MAXN];
__device__ int   g_psum  [4][64];
__device__ int   g_total [4];
__device__ int   g_csr_src[4][EMAX];
__device__ float g_csr_c [4][EMAX];
__device__ __align__(16) float g_dinv[4][MAXN];
__device__ __align__(16) float g_rels[4][D];
__device__ double g_sum[4][D];
__device__ double g_sumsq[4][D];
__device__ __align__(16) float g_scale[4][D];
__device__ __align__(16) float g_shift[4][D];
__device__ double g_scores[4];
__device__ float  g_coef[4];

// ---------------- helpers ----------------
__device__ __forceinline__ uint32_t f2tf(float x) {
    uint32_t u;
    asm("cvt.rna.tf32.f32 %0, %1;" : "=r"(u) : "f"(x));
    return u;
}
__device__ __forceinline__ void mma_tf32(float* c, const uint32_t* a, const uint32_t* b) {
    asm volatile(
        "mma.sync.aligned.m16n8k8.row.col.f32.tf32.tf32.f32 "
        "{%0,%1,%2,%3}, {%4,%5,%6,%7}, {%8,%9}, {%0,%1,%2,%3};"
        : "+f"(c[0]), "+f"(c[1]), "+f"(c[2]), "+f"(c[3])
        : "r"(a[0]), "r"(a[1]), "r"(a[2]), "r"(a[3]), "r"(b[0]), "r"(b[1]));
}
__device__ __forceinline__ void cp16(uint32_t dst, const void* src) {
    asm volatile("cp.async.cg.shared.global [%0], [%1], 16;" :: "r"(dst), "l"(src));
}

// ---------------- init: emb[0] = features; permute rels; zero counters/stats/scores ----
__global__ void k_init(const float* __restrict__ feat, const float* __restrict__ rel_emb, int Nn) {
    size_t idx = (size_t)blockIdx.x * blockDim.x + threadIdx.x;
    size_t tot = (size_t)Nn * D;
    if (idx < tot) {
        g_emb[0][idx] = feat[idx];
    }
    if (idx < 4 * (size_t)MAXN) ((int*)g_cnt)[idx] = 0;
    if (idx < 4 * D) {
        const int perm[4] = {3, 0, 1, 2};
        int r = (int)(idx / D), j = (int)(idx % D);
        g_rels[r][j] = rel_emb[perm[r] * D + j];
        ((double*)g_sum)[idx] = 0.0;
        ((double*)g_sumsq)[idx] = 0.0;
    }
    if (idx < 4) g_scores[idx] = 0.0;
}

// zero scratch tail rows [Nn, MAXN) so GEMM A-loads need no bounds checks
__global__ void k_zero_tail(int Nn) {
    size_t tail = (size_t)(MAXN - Nn) * D;
    size_t idx = (size_t)blockIdx.x * blockDim.x + threadIdx.x;
    if (idx >= tail) return;
    size_t o = (size_t)Nn * D + idx;
    #pragma unroll
    for (int r = 0; r < 4; r++) { g_emb[r][o] = 0.f; g_h[r][o] = 0.f; g_agg[r][o] = 0.f; }
}

// ---------------- CSR build ----------------
__global__ void k_hist(const int* __restrict__ edge, int E) {
    const int perm[4] = {3, 0, 1, 2};
    int r = blockIdx.y;
    const int* dst = edge + ((size_t)perm[r] * 2 + 1) * E;
    int t = blockIdx.x * blockDim.x + threadIdx.x;
    if (t < E) atomicAdd(&g_cnt[r][dst[t]], 1);
}

__global__ void k_scan1(int Nn) {     // grid (nb, 4) x 1024; also computes dinv
    int r = blockIdx.y, t = threadIdx.x;
    int i = blockIdx.x * 1024 + t;
    int v = (i < Nn) ? g_cnt[r][i] : 0;
    if (i < Nn) g_dinv[r][i] = rsqrtf((float)v + 1.0f);
    int x = v;
    #pragma unroll
    for (int o = 1; o < 32; o <<= 1) {
        int y = __shfl_up_sync(0xFFFFFFFFu, x, o);
        if ((t & 31) >= o) x += y;
    }
    __shared__ int ws[32];
    if ((t & 31) == 31) ws[t >> 5] = x;
    __syncthreads();
    if (t < 32) {
        int y = ws[t];
        #pragma unroll
        for (int o = 1; o < 32; o <<= 1) {
            int z = __shfl_up_sync(0xFFFFFFFFu, y, o);
            if (t >= o) y += z;
        }
        ws[t] = y;
    }
    __syncthreads();
    int off = (t >= 32) ? ws[(t >> 5) - 1] : 0;
    int incl = x + off;
    if (i < Nn) g_rowptr[r][i] = incl - v;
    if (t == 1023) g_psum[r][blockIdx.x] = incl;
}

__global__ void k_scan2(int nb) {     // grid 4 x 64
    int r = blockIdx.x, t = threadIdx.x;
    int v = (t < nb) ? g_psum[r][t] : 0;
    int x = v;
    #pragma unroll
    for (int o = 1; o < 32; o <<= 1) {
        int y = __shfl_up_sync(0xFFFFFFFFu, x, o);
        if ((t & 31) >= o) x += y;
    }
    __shared__ int w2[2];
    if ((t & 31) == 31) w2[t >> 5] = x;
    __syncthreads();
    int off = (t >= 32) ? w2[0] : 0;
    int incl = x + off;
    g_psum[r][t] = incl - v;
    if (t == 63) g_total[r] = incl;
}

__global__ void k_scan3(int Nn) {     // grid (nb, 4) x 1024
    int r = blockIdx.y;
    int i = blockIdx.x * 1024 + threadIdx.x;
    if (i < Nn) {
        int val = g_rowptr[r][i] + g_psum[r][blockIdx.x];
        g_rowptr[r][i] = val;
        g_wofs[r][i] = val;
    }
    if (i == 0) g_rowptr[r][Nn] = g_total[r];
}

__global__ void k_fill(const int* __restrict__ edge, int E) {
    const int perm[4] = {3, 0, 1, 2};
    int r = blockIdx.y;
    const int* src = edge + ((size_t)perm[r] * 2) * E;
    const int* dst = src + E;
    int e = blockIdx.x * blockDim.x + threadIdx.x;
    if (e >= E) return;
    int s = src[e], d = dst[e];
    int pos = atomicAdd(&g_wofs[r][d], 1);
    g_csr_src[r][pos] = s;
    g_csr_c[r][pos] = g_dinv[r][s] * g_dinv[r][d];
}

// ---------------- batched pipelined TF32 GEMM ----------------
// BM=128 BN=128 BK=32, 256 threads, cp.async 2-stage double buffer.
// z = blockIdx.z selects batch slice via long4 offsets.
// EPI: 0 plain store (+bias), 1 blend (C = (acc+bias)*alpha[z] + (1-alpha)*stk),
//      2 score (no store; sum lrelu(acc+bias)*q -> scores[z]).
template <bool TRANSB, bool SCALE_A, bool BIAS, int EPI>
__global__ void __launch_bounds__(256) k_gemm_tf32(
    const float* __restrict__ A_base, long4 a_off,
    const float* __restrict__ Bm,
    float* __restrict__ C_base, long4 c_off,
    int M, int N, int K,
    const float* __restrict__ cs_base,
    const float* __restrict__ bias,
    const float* __restrict__ ep_base, long4 ep_off,
    const float* __restrict__ alphas,
    double* __restrict__ scores)
{
    extern __shared__ uint32_t sm[];
    __shared__ float s_cs[128];
    const int tid = threadIdx.x;
    const int lane = tid & 31, wid = tid >> 5;
    const int z = blockIdx.z;
    const long ao = (z == 0) ? a_off.x : (z == 1) ? a_off.y : (z == 2) ? a_off.z : a_off.w;
    const long co = (z == 0) ? c_off.x : (z == 1) ? c_off.y : (z == 2) ? c_off.z : c_off.w;
    const long eo = (z == 0) ? ep_off.x : (z == 1) ? ep_off.y : (z == 2) ? ep_off.z : ep_off.w;
    const float* A = A_base + ao;
    float* C = C_base + co;
    const int bm = blockIdx.y * 128;
    const int bn = blockIdx.x * 128;
    const int warp_m = (wid & 3) * 32;
    const int warp_n = (wid >> 2) * 64;
    const uint32_t smem_u = (uint32_t)__cvta_generic_to_shared(sm);

    if (SCALE_A && tid < 128) s_cs[tid] = cs_base[z * 128 + tid];

    float acc[2][8][4];
    #pragma unroll
    for (int i = 0; i < 2; i++)
        #pragma unroll
        for (int j = 0; j < 8; j++)
            #pragma unroll
            for (int q = 0; q < 4; q++) acc[i][j][q] = 0.0f;

    auto load_stage = [&](int st, int k0) {
        #pragma unroll
        for (int i = 0; i < 4; i++) {
            int id = tid + i * 256;
            int m = id >> 3, c = id & 7;
            cp16(smem_u + (uint32_t)(st * 4608 + m * 36 + c * 4) * 4,
                 A + (size_t)(bm + m) * K + k0 + c * 4);
        }
        if (TRANSB) {
            #pragma unroll
            for (int i = 0; i < 4; i++) {
                int id = tid + i * 256;
                int n = id >> 3, c = id & 7;
                cp16(smem_u + (uint32_t)(9216 + st * 4608 + n * 36 + c * 4) * 4,
                     Bm + (size_t)(bn + n) * K + k0 + c * 4);
            }
        } else {
            #pragma unroll
            for (int i = 0; i < 4; i++) {
                int id = tid + i * 256;
                int k = id >> 5, c = id & 31;
                cp16(smem_u + (uint32_t)(9216 + st * 4352 + k * 136 + c * 4) * 4,
                     Bm + (size_t)(k0 + k) * N + bn + c * 4);
            }
        }
    };

    const int r0 = lane >> 2, c0 = lane & 3;
    const int nk = K >> 5;

    load_stage(0, 0);
    asm volatile("cp.async.commit_group;");

    for (int kt = 0; kt < nk; kt++) {
        const int cur = kt & 1;
        const int k0g = kt << 5;
        if (kt + 1 < nk) {
            load_stage((kt + 1) & 1, (kt + 1) << 5);
            asm volatile("cp.async.commit_group;");
            asm volatile("cp.async.wait_group 1;");
        } else {
            asm volatile("cp.async.wait_group 0;");
        }
        __syncthreads();

        #pragma unroll
        for (int ks = 0; ks < 32; ks += 8) {
            uint32_t a[2][4], b[8][2];
            float cs0 = 1.0f, cs1 = 1.0f;
            if (SCALE_A) { cs0 = s_cs[k0g + ks + c0]; cs1 = s_cs[k0g + ks + 4 + c0]; }
            #pragma unroll
            for (int fm = 0; fm < 2; fm++) {
                int mb = warp_m + fm * 16;
                const uint32_t* Ab = sm + cur * 4608;
                float v0 = __uint_as_float(Ab[(mb + r0) * 36 + ks + c0]);
                float v1 = __uint_as_float(Ab[(mb + 8 + r0) * 36 + ks + c0]);
                float v2 = __uint_as_float(Ab[(mb + r0) * 36 + ks + 4 + c0]);
                float v3 = __uint_as_float(Ab[(mb + 8 + r0) * 36 + ks + 4 + c0]);
                if (SCALE_A) { v0 *= cs0; v1 *= cs0; v2 *= cs1; v3 *= cs1; }
                a[fm][0] = f2tf(v0); a[fm][1] = f2tf(v1);
                a[fm][2] = f2tf(v2); a[fm][3] = f2tf(v3);
            }
            if (TRANSB) {
                const uint32_t* Bb = sm + 9216 + cur * 4608;
                #pragma unroll
                for (int fn = 0; fn < 8; fn++) {
                    int nb = warp_n + fn * 8 + r0;
                    b[fn][0] = f2tf(__uint_as_float(Bb[nb * 36 + ks + c0]));
                    b[fn][1] = f2tf(__uint_as_float(Bb[nb * 36 + ks + 4 + c0]));
                }
            } else {
                const uint32_t* Bb = sm + 9216 + cur * 4352;
                #pragma unroll
                for (int fn = 0; fn < 8; fn++) {
                    int nb = warp_n + fn * 8 + r0;
                    b[fn][0] = f2tf(__uint_as_float(Bb[(ks + c0) * 136 + nb]));
                    b[fn][1] = f2tf(__uint_as_float(Bb[(ks + 4 + c0) * 136 + nb]));
                }
            }
            #pragma unroll
            for (int fm = 0; fm < 2; fm++)
                #pragma unroll
                for (int fn = 0; fn < 8; fn++)
                    mma_tf32(acc[fm][fn], a[fm], b[fn]);
        }
        __syncthreads();
    }

    // ---- epilogue ----
    const int cc = (lane & 3) * 2;
    float alpha = 0.f, oma = 0.f;
    if (EPI == 1) { alpha = alphas[z]; oma = 1.0f - alpha; }
    const float* EP = (EPI != 0) ? (ep_base + (EPI == 1 ? eo : 0)) : nullptr;
    float score_local = 0.0f;

    #pragma unroll
    for (int fm = 0; fm < 2; fm++) {
        #pragma unroll
        for (int fn = 0; fn < 8; fn++) {
            int row = bm + warp_m + fm * 16 + r0;
            int col = bn + warp_n + fn * 8 + cc;
            float b0 = BIAS ? bias[col] : 0.0f;
            float b1 = BIAS ? bias[col + 1] : 0.0f;
            float v00 = acc[fm][fn][0] + b0, v01 = acc[fm][fn][1] + b1;
            float v10 = acc[fm][fn][2] + b0, v11 = acc[fm][fn][3] + b1;
            if (EPI == 0) {
                if (row < M)     *(float2*)(C + (size_t)row * N + col)       = make_float2(v00, v01);
                if (row + 8 < M) *(float2*)(C + (size_t)(row + 8) * N + col) = make_float2(v10, v11);
            } else if (EPI == 1) {
                if (row < M) {
                    float2 s = *(const float2*)(EP + (size_t)row * N + col);
                    *(float2*)(C + (size_t)row * N + col) =
                        make_float2(v00 * alpha + oma * s.x, v01 * alpha + oma * s.y);
                }
                if (row + 8 < M) {
                    float2 s = *(const float2*)(EP + (size_t)(row + 8) * N + col);
                    *(float2*)(C + (size_t)(row + 8) * N + col) =
                        make_float2(v10 * alpha + oma * s.x, v11 * alpha + oma * s.y);
                }
            } else {
                float q0 = EP[col], q1 = EP[col + 1];
                if (row < M) {
                    float l0 = v00 > 0.f ? v00 : 0.01f * v00;
                    float l1 = v01 > 0.f ? v01 : 0.01f * v01;
                    score_local += l0 * q0 + l1 * q1;
                }
                if (row + 8 < M) {
                    float l0 = v10 > 0.f ? v10 : 0.01f * v10;
                    float l1 = v11 > 0.f ? v11 : 0.01f * v11;
                    score_local += l0 * q0 + l1 * q1;
                }
            }
        }
    }

    if (EPI == 2) {
        __shared__ float sred[8];
        #pragma unroll
        for (int o = 16; o > 0; o >>= 1)
            score_local += __shfl_xor_sync(0xFFFFFFFFu, score_local, o);
        if (lane == 0) sred[wid] = score_local;
        __syncthreads();
        if (tid == 0) {
            float tot = 0.f;
            #pragma unroll
            for (int w = 0; w < 8; w++) tot += sred[w];
            atomicAdd(&scores[z], (double)tot);
        }
    }
}

// ---------------- CSR aggregation: persistent warps, 4-way unroll, fused BN stats ----
template <bool STATS>
__global__ void k_agg(const float* __restrict__ bias, int Nn) {
    int r = blockIdx.y;
    int lane = threadIdx.x & 31;
    int warp0 = blockIdx.x * (blockDim.x >> 5) + (threadIdx.x >> 5);
    int nwarps = gridDim.x * (blockDim.x >> 5);
    const float* h = g_h[r];
    const int* csr_src = g_csr_src[r];
    const float* csr_c = g_csr_c[r];
    float4 bv = ((const float4*)bias)[lane];

    double s0 = 0, s1 = 0, s2 = 0, s3 = 0;
    double q0 = 0, q1 = 0, q2 = 0, q3 = 0;

    for (int d = warp0; d < Nn; d += nwarps) {
        float di = g_dinv[r][d];
        float d2 = di * di;
        float4 acc = ((const float4*)(h + (size_t)d * D))[lane];
        acc.x = acc.x * d2 + bv.x;
        acc.y = acc.y * d2 + bv.y;
        acc.z = acc.z * d2 + bv.z;
        acc.w = acc.w * d2 + bv.w;
        int beg = g_rowptr[r][d], end = g_rowptr[r][d + 1];
        int e = beg;
        int end4 = beg + ((end - beg) & ~3);
        for (; e < end4; e += 4) {
            int sA = csr_src[e], sB = csr_src[e + 1], sC = csr_src[e + 2], sD = csr_src[e + 3];
            float cA = csr_c[e], cB = csr_c[e + 1], cC = csr_c[e + 2], cD = csr_c[e + 3];
            float4 hA = ((const float4*)(h + (size_t)sA * D))[lane];
            float4 hB = ((const float4*)(h + (size_t)sB * D))[lane];
            float4 hC = ((const float4*)(h + (size_t)sC * D))[lane];
            float4 hD = ((const float4*)(h + (size_t)sD * D))[lane];
            acc.x += hA.x * cA + hB.x * cB + hC.x * cC + hD.x * cD;
            acc.y += hA.y * cA + hB.y * cB + hC.y * cC + hD.y * cD;
            acc.z += hA.z * cA + hB.z * cB + hC.z * cC + hD.z * cD;
            acc.w += hA.w * cA + hB.w * cB + hC.w * cC + hD.w * cD;
        }
        for (; e < end; e++) {
            int s = csr_src[e];
            float c = csr_c[e];
            float4 hv = ((const float4*)(h + (size_t)s * D))[lane];
            acc.x += hv.x * c;
            acc.y += hv.y * c;
            acc.z += hv.z * c;
            acc.w += hv.w * c;
        }
        ((float4*)(g_agg[r] + (size_t)d * D))[lane] = acc;
        if (STATS) {
            s0 += acc.x; q0 += (double)acc.x * acc.x;
            s1 += acc.y; q1 += (double)acc.y * acc.y;
            s2 += acc.z; q2 += (double)acc.z * acc.z;
            s3 += acc.w; q3 += (double)acc.w * acc.w;
        }
    }

    if (STATS) {
        __shared__ double ssum[128], ssq[128];
        for (int t = threadIdx.x; t < 128; t += blockDim.x) { ssum[t] = 0.0; ssq[t] = 0.0; }
        __syncthreads();
        int c4 = lane * 4;
        atomicAdd(&ssum[c4 + 0], s0); atomicAdd(&ssq[c4 + 0], q0);
        atomicAdd(&ssum[c4 + 1], s1); atomicAdd(&ssq[c4 + 1], q1);
        atomicAdd(&ssum[c4 + 2], s2); atomicAdd(&ssq[c4 + 2], q2);
        atomicAdd(&ssum[c4 + 3], s3); atomicAdd(&ssq[c4 + 3], q3);
        __syncthreads();
        for (int t = threadIdx.x; t < 128; t += blockDim.x) {
            atomicAdd(&g_sum[r][t], ssum[t]);
            atomicAdd(&g_sumsq[r][t], ssq[t]);
        }
    }
}

// ---------------- BatchNorm finalize (re-zeros stats for the next layer) ----------------
__global__ void k_bn_final(const float* __restrict__ gamma, const float* __restrict__ beta, int Nn) {
    int t = threadIdx.x;   // 512
    int r = t >> 7, j = t & 127;
    double mean = g_sum[r][j] / Nn;
    double var = g_sumsq[r][j] / Nn - mean * mean;
    float sc = gamma[j] * (float)(1.0 / sqrt(var + 1e-5));
    g_scale[r][j] = sc;
    g_shift[r][j] = beta[j] - (float)mean * sc;
    g_sum[r][j] = 0.0;
    g_sumsq[r][j] = 0.0;
}

// emb[r] = base + lrelu(agg*scale+shift); base = features (layer0) or emb[r]
__global__ void k_bn_apply(const float* __restrict__ base, int Nn) {   // grid (g4, 4) x 256
    int r = blockIdx.y;
    size_t i4 = (size_t)blockIdx.x * blockDim.x + threadIdx.x;
    if (i4 >= (size_t)Nn * 32) return;
    int c4 = (int)(i4 & 31) * 4;
    float4 a = ((const float4*)g_agg[r])[i4];
    float4 sc = *(const float4*)(g_scale[r] + c4);
    float4 sh = *(const float4*)(g_shift[r] + c4);
    float4 v;
    v.x = a.x * sc.x + sh.x; v.x = v.x > 0.f ? v.x : 0.01f * v.x;
    v.y = a.y * sc.y + sh.y; v.y = v.y > 0.f ? v.y : 0.01f * v.y;
    v.z = a.z * sc.z + sh.z; v.z = v.z > 0.f ? v.z : 0.01f * v.z;
    v.w = a.w * sc.w + sh.w; v.w = v.w > 0.f ? v.w : 0.01f * v.w;
    float4 b = base ? ((const float4*)base)[i4] : ((const float4*)g_emb[r])[i4];
    v.x += b.x; v.y += b.y; v.z += b.z; v.w += b.w;
    ((float4*)g_emb[r])[i4] = v;
}

// ---------------- rels update ----------------
__global__ void k_rels_update(const float* __restrict__ Wrt, const float* __restrict__ brt) {
    __shared__ float cur[4 * D];
    int t = threadIdx.x;  // 512
    cur[t] = ((float*)g_rels)[t];
    __syncthreads();
    int r = t >> 7, j = t & 127;
    float s = brt[j];
    #pragma unroll 8
    for (int k = 0; k < D; k++) s = fmaf(cur[r * D + k], Wrt[j * D + k], s);
    ((float*)g_rels)[t] = s;
}

// ---------------- attention ----------------
__global__ void k_attn(int Nn) {
    int gw = (blockIdx.x * blockDim.x + threadIdx.x) >> 5;
    int lane = threadIdx.x & 31;
    if (gw >= Nn * 4) return;
    int n = gw >> 2, h = gw & 3;
    float q[4], kk[4], v[4];
    #pragma unroll
    for (int l = 0; l < 4; l++) {
        const float* base = g_qkv[l] + (size_t)n * 384 + h * 32 + lane;
        q[l]  = base[0] * 0.17677669529663687f;
        kk[l] = base[128];
        v[l]  = base[256];
    }
    float sc[4][4];
    #pragma unroll
    for (int l = 0; l < 4; l++)
        #pragma unroll
        for (int m = 0; m < 4; m++) {
            float p = q[l] * kk[m];
            p += __shfl_xor_sync(0xFFFFFFFFu, p, 16);
            p += __shfl_xor_sync(0xFFFFFFFFu, p, 8);
            p += __shfl_xor_sync(0xFFFFFFFFu, p, 4);
            p += __shfl_xor_sync(0xFFFFFFFFu, p, 2);
            p += __shfl_xor_sync(0xFFFFFFFFu, p, 1);
            sc[l][m] = p;
        }
    #pragma unroll
    for (int l = 0; l < 4; l++) {
        float mx = fmaxf(fmaxf(sc[l][0], sc[l][1]), fmaxf(sc[l][2], sc[l][3]));
        float e0 = expf(sc[l][0] - mx), e1 = expf(sc[l][1] - mx);
        float e2 = expf(sc[l][2] - mx), e3 = expf(sc[l][3] - mx);
        float inv = 1.0f / (e0 + e1 + e2 + e3);
        float o = (e0 * v[0] + e1 * v[1] + e2 * v[2] + e3 * v[3]) * inv;
        g_h[l][(size_t)n * D + h * 32 + lane] = o;
    }
}

// ---------------- coef ----------------
__global__ void k_coef(int Nn) {
    double sv[4] = { g_scores[0] / Nn, g_scores[1] / Nn, g_scores[3] / Nn, g_scores[2] / Nn };
    double mx = sv[0];
    for (int i = 1; i < 4; i++) mx = sv[i] > mx ? sv[i] : mx;
    double e[4], ss = 0.0;
    for (int i = 0; i < 4; i++) { e[i] = exp(sv[i] - mx); ss += e[i]; }
    double w[4];
    for (int i = 0; i < 4; i++) w[i] = e[i] / ss;
    g_coef[0] = (float)w[0];
    g_coef[1] = (float)w[1];
    g_coef[2] = (float)w[3];
    g_coef[3] = (float)w[2];
}

// ---------------- final outputs (float4) ----------------
__global__ void k_final(float* __restrict__ out, int Nn) {
    size_t i4 = (size_t)blockIdx.x * blockDim.x + threadIdx.x;
    size_t ND4 = (size_t)Nn * 32;
    if (i4 >= ND4) return;
    int c4 = (int)(i4 & 31) * 4;
    float4 e0 = ((const float4*)g_emb[0])[i4];
    float4 e1 = ((const float4*)g_emb[1])[i4];
    float4 e2 = ((const float4*)g_emb[2])[i4];
    float4 e3 = ((const float4*)g_emb[3])[i4];
    float w0 = g_coef[0], w1 = g_coef[1], w2 = g_coef[2], w3 = g_coef[3];
    float4 r4;
    r4.x = w0 * e0.x + w1 * e1.x + w2 * e2.x + w3 * e3.x;
    r4.y = w0 * e0.y + w1 * e1.y + w2 * e2.y + w3 * e3.y;
    r4.z = w0 * e0.z + w1 * e1.z + w2 * e2.z + w3 * e3.z;
    r4.w = w0 * e0.w + w1 * e1.w + w2 * e2.w + w3 * e3.w;
    float4* o4 = (float4*)out;
    o4[i4] = r4;
    float4 c;
    c = *(const float4*)(g_rels[3] + c4);
    o4[ND4 + i4]     = make_float4(r4.x * c.x, r4.y * c.y, r4.z * c.z, r4.w * c.w);
    c = *(const float4*)(g_rels[0] + c4);
    o4[2 * ND4 + i4] = make_float4(r4.x * c.x, r4.y * c.y, r4.z * c.z, r4.w * c.w);
    c = *(const float4*)(g_rels[1] + c4);
    o4[3 * ND4 + i4] = make_float4(r4.x * c.x, r4.y * c.y, r4.z * c.z, r4.w * c.w);
    c = *(const float4*)(g_rels[2] + c4);
    o4[4 * ND4 + i4] = make_float4(r4.x * c.x, r4.y * c.y, r4.z * c.z, r4.w * c.w);
}

// ---------------- host orchestration ----------------
extern "C" void kernel_launch(void* const* d_in, const int* in_sizes, int n_in,
                              void* d_out, int out_size) {
    const float* features   = (const float*)d_in[0];
    const float* rel_emb    = (const float*)d_in[1];
    const int*   edge_index = (const int*)  d_in[2];
    const float* W_gcn      = (const float*)d_in[3];
    const float* b_gcn      = (const float*)d_in[4];
    const float* bn_gamma   = (const float*)d_in[5];
    const float* bn_beta    = (const float*)d_in[6];
    const float* W_rt       = (const float*)d_in[7];
    const float* b_rt       = (const float*)d_in[8];
    const float* attn_w_in  = (const float*)d_in[9];
    const float* attn_b_in  = (const float*)d_in[10];
    const float* attn_w_out = (const float*)d_in[11];
    const float* attn_b_out = (const float*)d_in[12];
    const float* alphas     = (const float*)d_in[13];
    const float* fusion_q   = (const float*)d_in[14];
    const float* fusion_w   = (const float*)d_in[15];
    const float* fusion_b   = (const float*)d_in[16];

    int Nn = in_sizes[0] / D;
    int E  = in_sizes[2] / 8;
    if (Nn > MAXN || E > EMAX) return;

    static float *emb = nullptr, *h, *agg, *qkv, *rels;
    static double *scores;
    static bool attr_done = false;
    if (!emb) {
        cudaGetSymbolAddress((void**)&emb,    g_emb);
        cudaGetSymbolAddress((void**)&h,      g_h);
        cudaGetSymbolAddress((void**)&agg,    g_agg);
        cudaGetSymbolAddress((void**)&qkv,    g_qkv);
        cudaGetSymbolAddress((void**)&rels,   g_rels);
        cudaGetSymbolAddress((void**)&scores, g_scores);
    }
    const int SMEM_T  = 73728;
    const int SMEM_NT = 71680;
    if (!attr_done) {
        cudaFuncSetAttribute((const void*)k_gemm_tf32<false, true,  false, 0>,
                             cudaFuncAttributeMaxDynamicSharedMemorySize, SMEM_NT);
        cudaFuncSetAttribute((const void*)k_gemm_tf32<true,  false, true,  0>,
                             cudaFuncAttributeMaxDynamicSharedMemorySize, SMEM_T);
        cudaFuncSetAttribute((const void*)k_gemm_tf32<true,  false, true,  1>,
                             cudaFuncAttributeMaxDynamicSharedMemorySize, SMEM_T);
        cudaFuncSetAttribute((const void*)k_gemm_tf32<true,  false, true,  2>,
                             cudaFuncAttributeMaxDynamicSharedMemorySize, SMEM_T);
        attr_done = true;
    }

    const long S = (long)MAXN * D;
    const long Q = (long)MAXN * 384;
    const long4 ident = make_long4(0, S, 2 * S, 3 * S);
    const long4 smapo = make_long4(3 * S, 0, 2 * S, 1 * S);
    const long4 qoff  = make_long4(0, Q, 2 * Q, 3 * Q);
    const long4 zero4 = make_long4(0, 0, 0, 0);

    size_t ND = (size_t)Nn * D;
    int gElem = (int)((ND + TPB - 1) / TPB);
    int g4    = (int)(((size_t)Nn * 32 + TPB - 1) / TPB);
    int gEdge = (E + TPB - 1) / TPB;
    int gy    = (Nn + 127) / 128;
    int nb    = (Nn + 1023) / 1024;
    int gTail = (int)(((size_t)(MAXN - Nn) * D + TPB - 1) / TPB);

    k_init<<<gElem, TPB>>>(features, rel_emb, Nn);
    if (gTail > 0) k_zero_tail<<<gTail, TPB>>>(Nn);
    k_hist<<<dim3(gEdge, 4), TPB>>>(edge_index, E);
    k_scan1<<<dim3(nb, 4), 1024>>>(Nn);
    k_scan2<<<4, 64>>>(nb);
    k_scan3<<<dim3(nb, 4), 1024>>>(Nn);
    k_fill<<<dim3(gEdge, 4), TPB>>>(edge_index, E);

    for (int i = 0; i < 3; i++) {
        const float* Wg = W_gcn + (size_t)i * D * D;
        const float* bg = b_gcn + (size_t)i * D;
        // h[r] = (emb_src * rels[r]) @ Wg ; layer 0 reads emb[0] for all r
        k_gemm_tf32<false, true, false, 0><<<dim3(1, gy, 4), 256, SMEM_NT>>>(
            emb, (i == 0) ? zero4 : ident, Wg, h, ident, Nn, D, D,
            rels, nullptr, nullptr, zero4, nullptr, nullptr);
        if (i < 2) {
            k_agg<true><<<dim3(624, 4), TPB>>>(bg, Nn);
            k_bn_final<<<1, 512>>>(bn_gamma + (size_t)i * D, bn_beta + (size_t)i * D, Nn);
            k_bn_apply<<<dim3(g4, 4), TPB>>>((i == 0) ? features : nullptr, Nn);
        } else {
            k_agg<false><<<dim3(624, 4), TPB>>>(bg, Nn);
        }
        k_rels_update<<<1, 512>>>(W_rt + (size_t)i * D * D, b_rt + (size_t)i * D);
    }

    // QKV over stk[l] = agg[SMAP[l]]
    k_gemm_tf32<true, false, true, 0><<<dim3(3, gy, 4), 256, SMEM_T>>>(
        agg, smapo, attn_w_in, qkv, qoff, Nn, 384, D,
        nullptr, attn_b_in, nullptr, zero4, nullptr, nullptr);
    k_attn<<<(int)(((size_t)Nn * 128 + TPB - 1) / TPB), TPB>>>(Nn);
    // out-proj + fused blend -> emb[l]
    k_gemm_tf32<true, false, true, 1><<<dim3(1, gy, 4), 256, SMEM_T>>>(
        h, ident, attn_w_out, emb, ident, Nn, D, D,
        nullptr, attn_b_out, agg, smapo, alphas, nullptr);
    // fused score GEMMs
    k_gemm_tf32<true, false, true, 2><<<dim3(1, gy, 4), 256, SMEM_T>>>(
        emb, ident, fusion_w, h, ident, Nn, D, D,
        nullptr, fusion_b, fusion_q, zero4, nullptr, scores);
    k_coef<<<1, 1>>>(Nn);
    k_final<<<g4, TPB>>>((float*)d_out, Nn);
}